// round 5
// baseline (speedup 1.0000x reference)
#include <cuda_runtime.h>
#include <cuda_bf16.h>
#include <math.h>
#include <stdint.h>

#define D_MODEL   2048
#define KV_DIM    512
#define HEAD_DIM  64
#define NUM_HEADS 32
#define BATCH     2
#define SEQ       2048
#define M_TOT     (BATCH*SEQ)   // 4096

// ------------------- scratch (__device__ globals) ---------------------------
// int8 quantized activations (2 digits each)
__device__ int8_t s_q1q[(size_t)M_TOT * D_MODEL];
__device__ int8_t s_q2q[(size_t)M_TOT * D_MODEL];
__device__ int8_t s_q1k[(size_t)M_TOT * D_MODEL];
__device__ int8_t s_q2k[(size_t)M_TOT * D_MODEL];
__device__ int8_t s_q1v[(size_t)M_TOT * D_MODEL];
__device__ int8_t s_q2v[(size_t)M_TOT * D_MODEL];
__device__ int8_t s_q1a[(size_t)M_TOT * D_MODEL];
__device__ int8_t s_q2a[(size_t)M_TOT * D_MODEL];
// int8 quantized transposed weights W^T [N][K]
__device__ int8_t s_q1wq[(size_t)D_MODEL * D_MODEL];
__device__ int8_t s_q2wq[(size_t)D_MODEL * D_MODEL];
__device__ int8_t s_q1wk[(size_t)KV_DIM * D_MODEL];
__device__ int8_t s_q2wk[(size_t)KV_DIM * D_MODEL];
__device__ int8_t s_q1wv[(size_t)KV_DIM * D_MODEL];
__device__ int8_t s_q2wv[(size_t)KV_DIM * D_MODEL];
__device__ int8_t s_q1wo[(size_t)D_MODEL * D_MODEL];
__device__ int8_t s_q2wo[(size_t)D_MODEL * D_MODEL];
// scales
__device__ float f_sq[M_TOT];
__device__ float f_sk[M_TOT];
__device__ float f_sv[M_TOT];
__device__ float f_sa[M_TOT];
__device__ float f_swq[D_MODEL];
__device__ float f_swk[KV_DIM];
__device__ float f_swv[KV_DIM];
__device__ float f_swo[D_MODEL];
// projected tensors (split bf16, attention-ready layouts)
__device__ __nv_bfloat16 g_Qh[(size_t)M_TOT * D_MODEL];       // [m][2048] pre-scaled
__device__ __nv_bfloat16 g_Ql[(size_t)M_TOT * D_MODEL];
__device__ __nv_bfloat16 g_KhT[(size_t)16 * HEAD_DIM * SEQ];  // [bg][d][t]
__device__ __nv_bfloat16 g_KlT[(size_t)16 * HEAD_DIM * SEQ];
__device__ __nv_bfloat16 g_Vh [(size_t)M_TOT * KV_DIM];       // [m][512]
__device__ __nv_bfloat16 g_Vl [(size_t)M_TOT * KV_DIM];
// attention output (fp32)
__device__ float g_AOf[(size_t)M_TOT * D_MODEL];

// ------------------------------ helpers -------------------------------------
__device__ __forceinline__ uint32_t sptr(const void* p) {
    return (uint32_t)__cvta_generic_to_shared(p);
}
__device__ __forceinline__ void cp16(void* dst, const void* src) {
    asm volatile("cp.async.cg.shared.global [%0], [%1], 16;"
                 :: "r"(sptr(dst)), "l"(src));
}
__device__ __forceinline__ void cp_commit() { asm volatile("cp.async.commit_group;"); }
template<int N_> __device__ __forceinline__ void cp_wait() {
    asm volatile("cp.async.wait_group %0;" :: "n"(N_));
}
__device__ __forceinline__ void ldmA(uint32_t* r, uint32_t a) {
    asm volatile("ldmatrix.sync.aligned.m8n8.x4.shared.b16 {%0,%1,%2,%3}, [%4];"
                 : "=r"(r[0]), "=r"(r[1]), "=r"(r[2]), "=r"(r[3]) : "r"(a));
}
__device__ __forceinline__ void ldmBT(uint32_t* r, uint32_t a) {
    asm volatile("ldmatrix.sync.aligned.m8n8.x4.trans.shared.b16 {%0,%1,%2,%3}, [%4];"
                 : "=r"(r[0]), "=r"(r[1]), "=r"(r[2]), "=r"(r[3]) : "r"(a));
}
__device__ __forceinline__ void mma16816(float* c, const uint32_t* a, const uint32_t* b) {
    asm volatile("mma.sync.aligned.m16n8k16.row.col.f32.bf16.bf16.f32 "
                 "{%0,%1,%2,%3}, {%4,%5,%6,%7}, {%8,%9}, {%0,%1,%2,%3};"
                 : "+f"(c[0]), "+f"(c[1]), "+f"(c[2]), "+f"(c[3])
                 : "r"(a[0]), "r"(a[1]), "r"(a[2]), "r"(a[3]), "r"(b[0]), "r"(b[1]));
}
__device__ __forceinline__ void imma(int* c, const uint32_t* a, const uint32_t* b) {
    asm volatile("mma.sync.aligned.m16n8k32.row.col.s32.s8.s8.s32 "
                 "{%0,%1,%2,%3}, {%4,%5,%6,%7}, {%8,%9}, {%0,%1,%2,%3};"
                 : "+r"(c[0]), "+r"(c[1]), "+r"(c[2]), "+r"(c[3])
                 : "r"(a[0]), "r"(a[1]), "r"(a[2]), "r"(a[3]), "r"(b[0]), "r"(b[1]));
}
__device__ __forceinline__ void split2(float x, __nv_bfloat16& hi, __nv_bfloat16& lo) {
    hi = __float2bfloat16(x);
    lo = __float2bfloat16(x - __bfloat162float(hi));
}
__device__ __forceinline__ __nv_bfloat162 mk2(__nv_bfloat16 a, __nv_bfloat16 b) {
    __nv_bfloat162 r; r.x = a; r.y = b; return r;
}

// ------------------------- quantization kernels ------------------------------
// per-row double-digit int8: x = s*(q1 + q2/256), s = rowmax/127
__global__ __launch_bounds__(256) void quant_rows(
    const float* __restrict__ X, int8_t* __restrict__ Q1, int8_t* __restrict__ Q2,
    float* __restrict__ S, int K)
{
    const int row = blockIdx.x, tid = threadIdx.x;
    const float* x = X + (size_t)row * K;
    float am = 0.f;
    for (int i = tid; i < K; i += 256) am = fmaxf(am, fabsf(x[i]));
#pragma unroll
    for (int o = 16; o; o >>= 1) am = fmaxf(am, __shfl_xor_sync(~0u, am, o));
    __shared__ float red[8];
    __shared__ float amax_sh;
    if ((tid & 31) == 0) red[tid >> 5] = am;
    __syncthreads();
    if (tid == 0) {
        float m = red[0];
#pragma unroll
        for (int i = 1; i < 8; i++) m = fmaxf(m, red[i]);
        amax_sh = m;
        S[row] = m * (1.f / 127.f);
    }
    __syncthreads();
    float amax = amax_sh;
    float inv = amax > 0.f ? 127.f / amax : 0.f;
    for (int i = tid; i < K; i += 256) {
        float y = x[i] * inv;
        int q1 = __float2int_rn(y);
        float r = y - (float)q1;
        int q2 = __float2int_rn(256.f * r);
        q2 = max(-127, min(127, q2));
        Q1[(size_t)row * K + i] = (int8_t)q1;
        Q2[(size_t)row * K + i] = (int8_t)q2;
    }
}
// per-output-column amax of W[K][N]
__global__ void wcol_amax(const float* __restrict__ W, float* __restrict__ S,
                          int K, int N) {
    int n = blockIdx.x * 256 + threadIdx.x;
    if (n >= N) return;
    float am = 0.f;
    for (int k = 0; k < K; k++) am = fmaxf(am, fabsf(W[(size_t)k * N + n]));
    S[n] = am * (1.f / 127.f);
}
// W[K][N] -> quantized W^T [N][K]
__global__ void wtquant(const float* __restrict__ W, const float* __restrict__ S,
                        int8_t* __restrict__ Q1, int8_t* __restrict__ Q2,
                        int K, int N) {
    __shared__ float tile[32][33];
    int k0 = blockIdx.y * 32, n0 = blockIdx.x * 32;
    int tx = threadIdx.x, ty = threadIdx.y;
#pragma unroll
    for (int i = ty; i < 32; i += 8)
        tile[i][tx] = W[(size_t)(k0 + i) * N + n0 + tx];
    __syncthreads();
#pragma unroll
    for (int i = ty; i < 32; i += 8) {
        int n = n0 + i, k = k0 + tx;
        float s = S[n];
        float inv = s > 0.f ? 1.f / s : 0.f;
        float y = tile[tx][i] * inv;
        int q1 = __float2int_rn(y);
        float r = y - (float)q1;
        int q2 = __float2int_rn(256.f * r);
        q2 = max(-127, min(127, q2));
        Q1[(size_t)n * K + k] = (int8_t)q1;
        Q2[(size_t)n * K + k] = (int8_t)q2;
    }
}

// --------------------------- int8 double-digit GEMM --------------------------
// C[m][n] = Sa[m]*Sb[n]*(q1a·q1b + (q1a·q2b + q2a·q1b)/256) + bias[n]
// 128x128 tile, K-stage 64 bytes, 2-stage cp.async, 256 threads (8 warps 2x4).
// mode: 0 = f32 out; 1 = Q (0.125*, split); 2 = V (split); 3 = K (split+transpose)
#define ISTR 80            // smem row stride bytes (64B data + pad, conflict-free)
#define IARR (128*ISTR)    // 10240 per array
#define ISTG (4*IARR)      // 40960 per stage

__global__ __launch_bounds__(256, 1) void gemm_i8(
    const int8_t* __restrict__ q1a, const int8_t* __restrict__ q2a,
    const int8_t* __restrict__ q1b, const int8_t* __restrict__ q2b,
    const float* __restrict__ Sa, const float* __restrict__ Sb,
    const float* __restrict__ bias,
    __nv_bfloat16* __restrict__ Chi, __nv_bfloat16* __restrict__ Clo,
    float* __restrict__ Cf, int N, int mode)
{
    extern __shared__ char sm[];
    const int tid = threadIdx.x, lane = tid & 31, wid = tid >> 5;
    const int wm = wid >> 2, wn = wid & 3;      // 2x4 warps, warp tile 64x32
    const int rowBase = blockIdx.y * 128, colBase = blockIdx.x * 128;

    int acc0[4][4][4], accm[4][4][4];
#pragma unroll
    for (int a = 0; a < 4; a++)
#pragma unroll
        for (int b = 0; b < 4; b++)
#pragma unroll
            for (int c = 0; c < 4; c++) { acc0[a][b][c] = 0; accm[a][b][c] = 0; }

    auto fill = [&](int s, int t) {
        const int k0 = t * 64;
        char* base = sm + s * ISTG;
#pragma unroll
        for (int h = 0; h < 2; h++) {
            int cc = tid + h * 256;
            int r = cc >> 2, ch = cc & 3;
            int off = r * ISTR + ch * 16;
            size_t ga = (size_t)(rowBase + r) * D_MODEL + k0 + ch * 16;
            size_t gb = (size_t)(colBase + r) * D_MODEL + k0 + ch * 16;
            cp16(base + off,            q1a + ga);
            cp16(base + IARR + off,     q2a + ga);
            cp16(base + 2*IARR + off,   q1b + gb);
            cp16(base + 3*IARR + off,   q2b + gb);
        }
    };

    const int NT = D_MODEL / 64;   // 32
    fill(0, 0); cp_commit();

    for (int t = 0; t < NT; t++) {
        const int cur = t & 1;
        if (t + 1 < NT) { fill(1 - cur, t + 1); cp_commit(); cp_wait<1>(); }
        else cp_wait<0>();
        __syncthreads();

        const char* st = sm + cur * ISTG;
#pragma unroll
        for (int kc = 0; kc < 2; kc++) {
            uint32_t a1[4][4], a2[4][4], b1[2][4], b2[2][4];
#pragma unroll
            for (int mi = 0; mi < 4; mi++) {
                uint32_t ad = sptr(st + (wm * 64 + mi * 16 + (lane & 15)) * ISTR
                                   + kc * 32 + ((lane >> 4) * 16));
                ldmA(a1[mi], ad);
                ldmA(a2[mi], ad + IARR);
            }
#pragma unroll
            for (int j = 0; j < 2; j++) {
                int n = wn * 32 + j * 16 + ((lane >> 4) & 1) * 8 + (lane & 7);
                uint32_t bd = sptr(st + 2 * IARR + n * ISTR
                                   + kc * 32 + ((lane >> 3) & 1) * 16);
                ldmA(b1[j], bd);
                ldmA(b2[j], bd + IARR);
            }
#pragma unroll
            for (int mi = 0; mi < 4; mi++)
#pragma unroll
                for (int nj = 0; nj < 4; nj++) {
                    const int j = nj >> 1, hf = (nj & 1) * 2;
                    imma(acc0[mi][nj], a1[mi], &b1[j][hf]);
                    imma(accm[mi][nj], a1[mi], &b2[j][hf]);
                    imma(accm[mi][nj], a2[mi], &b1[j][hf]);
                }
        }
        __syncthreads();
    }

    // epilogue
    const float C256 = 1.f / 256.f;
#pragma unroll
    for (int mi = 0; mi < 4; mi++) {
        int row0 = rowBase + wm * 64 + mi * 16 + (lane >> 2);
        float sa0 = Sa[row0], sa1 = Sa[row0 + 8];
#pragma unroll
        for (int nj = 0; nj < 4; nj++) {
            int col = colBase + wn * 32 + nj * 8 + 2 * (lane & 3);
            float sb0 = Sb[col], sb1 = Sb[col + 1];
            float bx = bias[col], by = bias[col + 1];
            float v00 = ((float)acc0[mi][nj][0] + (float)accm[mi][nj][0] * C256) * sa0 * sb0 + bx;
            float v01 = ((float)acc0[mi][nj][1] + (float)accm[mi][nj][1] * C256) * sa0 * sb1 + by;
            float v10 = ((float)acc0[mi][nj][2] + (float)accm[mi][nj][2] * C256) * sa1 * sb0 + bx;
            float v11 = ((float)acc0[mi][nj][3] + (float)accm[mi][nj][3] * C256) * sa1 * sb1 + by;
            if (mode == 0) {
                *reinterpret_cast<float2*>(Cf + (size_t)row0 * N + col) = make_float2(v00, v01);
                *reinterpret_cast<float2*>(Cf + (size_t)(row0 + 8) * N + col) = make_float2(v10, v11);
            } else {
                if (mode == 1) { v00 *= 0.125f; v01 *= 0.125f; v10 *= 0.125f; v11 *= 0.125f; }
                __nv_bfloat16 h00, l00, h01, l01, h10, l10, h11, l11;
                split2(v00, h00, l00); split2(v01, h01, l01);
                split2(v10, h10, l10); split2(v11, h11, l11);
                if (mode == 3) {
                    int b = row0 >> 11, tt = row0 & 2047;
                    int g = col >> 6,  d = col & 63;
                    size_t base0 = ((size_t)(b * 8 + g) * 64 + d) * SEQ;
                    size_t base1 = base0 + SEQ;
                    Chi[base0 + tt] = h00;       Clo[base0 + tt] = l00;
                    Chi[base1 + tt] = h01;       Clo[base1 + tt] = l01;
                    Chi[base0 + tt + 8] = h10;   Clo[base0 + tt + 8] = l10;
                    Chi[base1 + tt + 8] = h11;   Clo[base1 + tt + 8] = l11;
                } else {
                    *reinterpret_cast<__nv_bfloat162*>(Chi + (size_t)row0 * N + col) = mk2(h00, h01);
                    *reinterpret_cast<__nv_bfloat162*>(Clo + (size_t)row0 * N + col) = mk2(l00, l01);
                    *reinterpret_cast<__nv_bfloat162*>(Chi + (size_t)(row0 + 8) * N + col) = mk2(h10, h11);
                    *reinterpret_cast<__nv_bfloat162*>(Clo + (size_t)(row0 + 8) * N + col) = mk2(l10, l11);
                }
            }
        }
    }
}

// ----------------------- flash attention (2 heads / CTA, bf16 3-term) -------
#define FSTR 72
#define SSTR 68

__global__ __launch_bounds__(512) void gqa_flash_mma(
    const __nv_bfloat16* __restrict__ Qh, const __nv_bfloat16* __restrict__ Ql,
    const __nv_bfloat16* __restrict__ KhT, const __nv_bfloat16* __restrict__ KlT,
    const __nv_bfloat16* __restrict__ Vh, const __nv_bfloat16* __restrict__ Vl,
    float* __restrict__ AOf)
{
    extern __shared__ char smraw[];
    __nv_bfloat16* Qhi = (__nv_bfloat16*)smraw;
    __nv_bfloat16* Qlo = Qhi + 128 * FSTR;
    __nv_bfloat16* Khi = Qlo + 128 * FSTR;
    __nv_bfloat16* Klo = Khi + 2 * 64 * FSTR;
    __nv_bfloat16* Vhi = Klo + 2 * 64 * FSTR;
    __nv_bfloat16* Vlo = Vhi + 2 * 64 * FSTR;
    __nv_bfloat16* Phi = Vlo + 2 * 64 * FSTR;
    __nv_bfloat16* Plo = Phi + 128 * FSTR;
    float* Sf  = (float*)(Plo + 128 * FSTR);
    float* m_s = Sf + 128 * SSTR;
    float* l_s = m_s + 128;
    float* c_s = l_s + 128;

    const int tid = threadIdx.x, lane = tid & 31, wid = tid >> 5;
    const int wm = wid & 7, wn = wid >> 3;
    const int qblk = blockIdx.x, hp = blockIdx.y, b = blockIdx.z;
    const int g = hp >> 1;
    const size_t bg = (size_t)(b * 8 + g);
    const int g64 = g * 64;

    auto loadKV = [&](int st, int jb) {
        const int c = tid;
        const int r = c >> 3, off8 = (c & 7) * 8;
        size_t ksrc = (bg * 64 + r) * (size_t)SEQ + jb * 64 + off8;
        size_t vsrc = ((size_t)(b * SEQ + jb * 64 + r)) * KV_DIM + g64 + off8;
        cp16(Khi + st * 64 * FSTR + r * FSTR + off8, KhT + ksrc);
        cp16(Klo + st * 64 * FSTR + r * FSTR + off8, KlT + ksrc);
        cp16(Vhi + st * 64 * FSTR + r * FSTR + off8, Vh + vsrc);
        cp16(Vlo + st * 64 * FSTR + r * FSTR + off8, Vl + vsrc);
    };

    loadKV(0, 0); cp_commit();
#pragma unroll
    for (int h = 0; h < 2; h++) {
        int c = tid + h * 512;
        int r = c >> 3, off8 = (c & 7) * 8;
        size_t src = ((size_t)(b * SEQ + qblk * 64 + (r & 63))) * D_MODEL
                   + (hp * 2 + (r >> 6)) * 64 + off8;
        cp16(Qhi + r * FSTR + off8, Qh + src);
        cp16(Qlo + r * FSTR + off8, Ql + src);
    }
    cp_commit();

    if (tid < 128) { m_s[tid] = -1e30f; l_s[tid] = 0.f; }

    float o[4][4];
#pragma unroll
    for (int i = 0; i < 4; i++)
#pragma unroll
        for (int j = 0; j < 4; j++) o[i][j] = 0.f;

    const int rowa = wm * 16 + (lane >> 2);
    const uint32_t aoff = 8 * (lane >> 4);
    const int arow15 = lane & 15;

    for (int jb = 0; jb < SEQ / 64; jb++) {
        const int cur = jb & 1;
        if (jb + 1 < SEQ / 64) { loadKV(1 - cur, jb + 1); cp_commit(); cp_wait<1>(); }
        else cp_wait<0>();
        __syncthreads();

        const __nv_bfloat16* Kc_h = Khi + cur * 64 * FSTR;
        const __nv_bfloat16* Kc_l = Klo + cur * 64 * FSTR;
        const __nv_bfloat16* Vc_h = Vhi + cur * 64 * FSTR;
        const __nv_bfloat16* Vc_l = Vlo + cur * 64 * FSTR;

        float s[4][4];
#pragma unroll
        for (int i = 0; i < 4; i++)
#pragma unroll
            for (int j = 0; j < 4; j++) s[i][j] = 0.f;

#pragma unroll
        for (int p = 0; p < 3; p++) {
            const __nv_bfloat16* Aseg = (p == 2) ? Qlo : Qhi;
            const __nv_bfloat16* Bseg = (p == 1) ? Kc_l : Kc_h;
#pragma unroll
            for (int kk = 0; kk < 64; kk += 16) {
                uint32_t af[4], bf[2][4];
                ldmA(af, sptr(&Aseg[(wm * 16 + arow15) * FSTR + kk + aoff]));
#pragma unroll
                for (int j = 0; j < 2; j++)
                    ldmBT(bf[j], sptr(&Bseg[(kk + arow15) * FSTR + wn * 32 + j * 16 + aoff]));
#pragma unroll
                for (int nj = 0; nj < 4; nj++)
                    mma16816(s[nj], af, &bf[nj >> 1][(nj & 1) * 2]);
            }
        }
#pragma unroll
        for (int nj = 0; nj < 4; nj++) {
            int col = wn * 32 + nj * 8 + 2 * (lane & 3);
            *reinterpret_cast<float2*>(&Sf[rowa * SSTR + col]) = make_float2(s[nj][0], s[nj][1]);
            *reinterpret_cast<float2*>(&Sf[(rowa + 8) * SSTR + col]) = make_float2(s[nj][2], s[nj][3]);
        }
        __syncthreads();

        {
            int r = tid >> 2, i = tid & 3;
            float* srow = &Sf[r * SSTR + i * 16];
            float mold = m_s[r];
            float pm = -1e30f;
#pragma unroll
            for (int c = 0; c < 16; c++) pm = fmaxf(pm, srow[c]);
            pm = fmaxf(pm, __shfl_xor_sync(0xffffffffu, pm, 1));
            pm = fmaxf(pm, __shfl_xor_sync(0xffffffffu, pm, 2));
            float mx = fmaxf(mold, pm);
            float lsum = 0.f;
#pragma unroll
            for (int c = 0; c < 16; c++) {
                float p = __expf(srow[c] - mx);
                srow[c] = p; lsum += p;
            }
            lsum += __shfl_xor_sync(0xffffffffu, lsum, 1);
            lsum += __shfl_xor_sync(0xffffffffu, lsum, 2);
            if (i == 0) {
                float corr = __expf(mold - mx);
                l_s[r] = l_s[r] * corr + lsum;
                m_s[r] = mx;
                c_s[r] = corr;
            }
        }
        __syncthreads();

        for (int idx = tid; idx < 128 * 64; idx += 512) {
            int r = idx >> 6, t = idx & 63;
            split2(Sf[r * SSTR + t], Phi[r * FSTR + t], Plo[r * FSTR + t]);
        }
        __syncthreads();

        {
            float cr0 = c_s[rowa], cr1 = c_s[rowa + 8];
#pragma unroll
            for (int nj = 0; nj < 4; nj++) {
                o[nj][0] *= cr0; o[nj][1] *= cr0;
                o[nj][2] *= cr1; o[nj][3] *= cr1;
            }
        }
#pragma unroll
        for (int p = 0; p < 3; p++) {
            const __nv_bfloat16* Aseg = (p == 2) ? Plo : Phi;
            const __nv_bfloat16* Bseg = (p == 1) ? Vc_l : Vc_h;
#pragma unroll
            for (int kk = 0; kk < 64; kk += 16) {
                uint32_t af[4], bf[2][4];
                ldmA(af, sptr(&Aseg[(wm * 16 + arow15) * FSTR + kk + aoff]));
#pragma unroll
                for (int j = 0; j < 2; j++)
                    ldmBT(bf[j], sptr(&Bseg[(kk + arow15) * FSTR + wn * 32 + j * 16 + aoff]));
#pragma unroll
                for (int nj = 0; nj < 4; nj++)
                    mma16816(o[nj], af, &bf[nj >> 1][(nj & 1) * 2]);
            }
        }
        __syncthreads();
    }

    float il0 = 1.f / l_s[rowa], il1 = 1.f / l_s[rowa + 8];
    int head = hp * 2 + (rowa >> 6);
    size_t m0 = (size_t)(b * SEQ + qblk * 64 + (rowa & 63));
#pragma unroll
    for (int nj = 0; nj < 4; nj++) {
        int col = head * 64 + wn * 32 + nj * 8 + 2 * (lane & 3);
        *reinterpret_cast<float2*>(AOf + m0 * D_MODEL + col) =
            make_float2(o[nj][0] * il0, o[nj][1] * il0);
        *reinterpret_cast<float2*>(AOf + (m0 + 8) * D_MODEL + col) =
            make_float2(o[nj][2] * il1, o[nj][3] * il1);
    }
}

// -----------------------------------------------------------------------------
extern "C" void kernel_launch(void* const* d_in, const int* in_sizes, int n_in,
                              void* d_out, int out_size)
{
    (void)in_sizes; (void)n_in; (void)out_size;
    const float* q  = (const float*)d_in[0];
    const float* k  = (const float*)d_in[1];
    const float* v  = (const float*)d_in[2];
    const float* Wq = (const float*)d_in[3];
    const float* bq = (const float*)d_in[4];
    const float* Wk = (const float*)d_in[5];
    const float* bk = (const float*)d_in[6];
    const float* Wv = (const float*)d_in[7];
    const float* bv = (const float*)d_in[8];
    const float* Wo = (const float*)d_in[9];
    const float* bo = (const float*)d_in[10];
    float* out = (float*)d_out;

    int8_t *q1q,*q2q,*q1k,*q2k,*q1v,*q2v,*q1a,*q2a;
    int8_t *q1wq,*q2wq,*q1wk,*q2wk,*q1wv,*q2wv,*q1wo,*q2wo;
    float *sq,*sk,*sv,*sa,*swq,*swk,*swv,*swo;
    __nv_bfloat16 *Qh,*Ql,*KhT,*KlT,*Vh,*Vl;
    float *AOf;
    cudaGetSymbolAddress((void**)&q1q, s_q1q);  cudaGetSymbolAddress((void**)&q2q, s_q2q);
    cudaGetSymbolAddress((void**)&q1k, s_q1k);  cudaGetSymbolAddress((void**)&q2k, s_q2k);
    cudaGetSymbolAddress((void**)&q1v, s_q1v);  cudaGetSymbolAddress((void**)&q2v, s_q2v);
    cudaGetSymbolAddress((void**)&q1a, s_q1a);  cudaGetSymbolAddress((void**)&q2a, s_q2a);
    cudaGetSymbolAddress((void**)&q1wq, s_q1wq); cudaGetSymbolAddress((void**)&q2wq, s_q2wq);
    cudaGetSymbolAddress((void**)&q1wk, s_q1wk); cudaGetSymbolAddress((void**)&q2wk, s_q2wk);
    cudaGetSymbolAddress((void**)&q1wv, s_q1wv); cudaGetSymbolAddress((void**)&q2wv, s_q2wv);
    cudaGetSymbolAddress((void**)&q1wo, s_q1wo); cudaGetSymbolAddress((void**)&q2wo, s_q2wo);
    cudaGetSymbolAddress((void**)&sq, f_sq);   cudaGetSymbolAddress((void**)&sk, f_sk);
    cudaGetSymbolAddress((void**)&sv, f_sv);   cudaGetSymbolAddress((void**)&sa, f_sa);
    cudaGetSymbolAddress((void**)&swq, f_swq); cudaGetSymbolAddress((void**)&swk, f_swk);
    cudaGetSymbolAddress((void**)&swv, f_swv); cudaGetSymbolAddress((void**)&swo, f_swo);
    cudaGetSymbolAddress((void**)&Qh,  g_Qh);  cudaGetSymbolAddress((void**)&Ql,  g_Ql);
    cudaGetSymbolAddress((void**)&KhT, g_KhT); cudaGetSymbolAddress((void**)&KlT, g_KlT);
    cudaGetSymbolAddress((void**)&Vh,  g_Vh);  cudaGetSymbolAddress((void**)&Vl,  g_Vl);
    cudaGetSymbolAddress((void**)&AOf, g_AOf);

    const size_t i8_smem = 2 * (size_t)ISTG;   // 81920
    cudaFuncSetAttribute(gemm_i8, cudaFuncAttributeMaxDynamicSharedMemorySize,
                         (int)i8_smem);
    const size_t flash_smem =
        (2 * 128 * FSTR + 4 * 2 * 64 * FSTR + 2 * 128 * FSTR) * sizeof(__nv_bfloat16)
        + (128 * SSTR + 3 * 128) * sizeof(float);
    cudaFuncSetAttribute(gqa_flash_mma, cudaFuncAttributeMaxDynamicSharedMemorySize,
                         (int)flash_smem);

    // quantize activations + weights
    quant_rows<<<M_TOT, 256>>>(q, q1q, q2q, sq, D_MODEL);
    quant_rows<<<M_TOT, 256>>>(k, q1k, q2k, sk, D_MODEL);
    quant_rows<<<M_TOT, 256>>>(v, q1v, q2v, sv, D_MODEL);
    wcol_amax<<<D_MODEL/256, 256>>>(Wq, swq, D_MODEL, D_MODEL);
    wcol_amax<<<KV_DIM/256,  256>>>(Wk, swk, D_MODEL, KV_DIM);
    wcol_amax<<<KV_DIM/256,  256>>>(Wv, swv, D_MODEL, KV_DIM);
    wcol_amax<<<D_MODEL/256, 256>>>(Wo, swo, D_MODEL, D_MODEL);
    wtquant<<<dim3(D_MODEL/32, D_MODEL/32), dim3(32,8)>>>(Wq, swq, q1wq, q2wq, D_MODEL, D_MODEL);
    wtquant<<<dim3(KV_DIM/32,  D_MODEL/32), dim3(32,8)>>>(Wk, swk, q1wk, q2wk, D_MODEL, KV_DIM);
    wtquant<<<dim3(KV_DIM/32,  D_MODEL/32), dim3(32,8)>>>(Wv, swv, q1wv, q2wv, D_MODEL, KV_DIM);
    wtquant<<<dim3(D_MODEL/32, D_MODEL/32), dim3(32,8)>>>(Wo, swo, q1wo, q2wo, D_MODEL, D_MODEL);

    // projections (int8 double-digit IMMA)
    gemm_i8<<<dim3(D_MODEL/128, M_TOT/128), 256, i8_smem>>>(
        q1q, q2q, q1wq, q2wq, sq, swq, bq, Qh, Ql, nullptr, D_MODEL, 1);
    gemm_i8<<<dim3(KV_DIM/128, M_TOT/128), 256, i8_smem>>>(
        q1k, q2k, q1wk, q2wk, sk, swk, bk, KhT, KlT, nullptr, KV_DIM, 3);
    gemm_i8<<<dim3(KV_DIM/128, M_TOT/128), 256, i8_smem>>>(
        q1v, q2v, q1wv, q2wv, sv, swv, bv, Vh, Vl, nullptr, KV_DIM, 2);

    // attention (bf16 3-term, 2 heads per CTA)
    gqa_flash_mma<<<dim3(SEQ / 64, NUM_HEADS / 2, BATCH), 512, flash_smem>>>(
        Qh, Ql, KhT, KlT, Vh, Vl, AOf);

    // output projection
    quant_rows<<<M_TOT, 256>>>(AOf, q1a, q2a, sa, D_MODEL);
    gemm_i8<<<dim3(D_MODEL/128, M_TOT/128), 256, i8_smem>>>(
        q1a, q2a, q1wo, q2wo, sa, swo, bo, nullptr, nullptr, out, D_MODEL, 0);
}

// round 9
// speedup vs baseline: 1.1862x; 1.1862x over previous
#include <cuda_runtime.h>
#include <cuda_bf16.h>
#include <math.h>
#include <stdint.h>

#define D_MODEL   2048
#define KV_DIM    512
#define HEAD_DIM  64
#define NUM_HEADS 32
#define BATCH     2
#define SEQ       2048
#define M_TOT     (BATCH*SEQ)   // 4096
#define K3        (3*D_MODEL)   // 6144 (3-pass split-K)

// ---------------- scratch (__device__ globals; no allocation) ---------------
__device__ __nv_bfloat16 s_qih[(size_t)M_TOT * D_MODEL];
__device__ __nv_bfloat16 s_qil[(size_t)M_TOT * D_MODEL];
__device__ __nv_bfloat16 s_kih[(size_t)M_TOT * D_MODEL];
__device__ __nv_bfloat16 s_kil[(size_t)M_TOT * D_MODEL];
__device__ __nv_bfloat16 s_vih[(size_t)M_TOT * D_MODEL];
__device__ __nv_bfloat16 s_vil[(size_t)M_TOT * D_MODEL];
__device__ __nv_bfloat16 s_wqh[(size_t)D_MODEL * D_MODEL];
__device__ __nv_bfloat16 s_wql[(size_t)D_MODEL * D_MODEL];
__device__ __nv_bfloat16 s_wkh[(size_t)D_MODEL * KV_DIM];
__device__ __nv_bfloat16 s_wkl[(size_t)D_MODEL * KV_DIM];
__device__ __nv_bfloat16 s_wvh[(size_t)D_MODEL * KV_DIM];
__device__ __nv_bfloat16 s_wvl[(size_t)D_MODEL * KV_DIM];
__device__ __nv_bfloat16 s_woh[(size_t)D_MODEL * D_MODEL];
__device__ __nv_bfloat16 s_wol[(size_t)D_MODEL * D_MODEL];
__device__ __nv_bfloat16 g_Qh[(size_t)M_TOT * D_MODEL];           // [m][2048] pre-scaled
__device__ __nv_bfloat16 g_Ql[(size_t)M_TOT * D_MODEL];
__device__ __nv_bfloat16 g_KhT[(size_t)16 * HEAD_DIM * SEQ];      // [bg][d][t]
__device__ __nv_bfloat16 g_KlT[(size_t)16 * HEAD_DIM * SEQ];
__device__ __nv_bfloat16 g_Vh [(size_t)M_TOT * KV_DIM];           // [m][512]
__device__ __nv_bfloat16 g_Vl [(size_t)M_TOT * KV_DIM];
__device__ __nv_bfloat16 g_AOh[(size_t)M_TOT * D_MODEL];
__device__ __nv_bfloat16 g_AOl[(size_t)M_TOT * D_MODEL];

// ------------------------------ helpers -------------------------------------
__device__ __forceinline__ uint32_t sptr(const void* p) {
    return (uint32_t)__cvta_generic_to_shared(p);
}
__device__ __forceinline__ void cp16(void* dst, const void* src) {
    asm volatile("cp.async.cg.shared.global [%0], [%1], 16;"
                 :: "r"(sptr(dst)), "l"(src));
}
__device__ __forceinline__ void cp_commit() { asm volatile("cp.async.commit_group;"); }
template<int N_> __device__ __forceinline__ void cp_wait() {
    asm volatile("cp.async.wait_group %0;" :: "n"(N_));
}
__device__ __forceinline__ void ldmA(uint32_t* r, uint32_t a) {
    asm volatile("ldmatrix.sync.aligned.m8n8.x4.shared.b16 {%0,%1,%2,%3}, [%4];"
                 : "=r"(r[0]), "=r"(r[1]), "=r"(r[2]), "=r"(r[3]) : "r"(a));
}
__device__ __forceinline__ void ldmBT(uint32_t* r, uint32_t a) {
    asm volatile("ldmatrix.sync.aligned.m8n8.x4.trans.shared.b16 {%0,%1,%2,%3}, [%4];"
                 : "=r"(r[0]), "=r"(r[1]), "=r"(r[2]), "=r"(r[3]) : "r"(a));
}
__device__ __forceinline__ void mma16816(float* c, const uint32_t* a, const uint32_t* b) {
    asm volatile("mma.sync.aligned.m16n8k16.row.col.f32.bf16.bf16.f32 "
                 "{%0,%1,%2,%3}, {%4,%5,%6,%7}, {%8,%9}, {%0,%1,%2,%3};"
                 : "+f"(c[0]), "+f"(c[1]), "+f"(c[2]), "+f"(c[3])
                 : "r"(a[0]), "r"(a[1]), "r"(a[2]), "r"(a[3]), "r"(b[0]), "r"(b[1]));
}
__device__ __forceinline__ void split2(float x, __nv_bfloat16& hi, __nv_bfloat16& lo) {
    hi = __float2bfloat16(x);
    lo = __float2bfloat16(x - __bfloat162float(hi));
}
__device__ __forceinline__ __nv_bfloat162 mk2(__nv_bfloat16 a, __nv_bfloat16 b) {
    __nv_bfloat162 r; r.x = a; r.y = b; return r;
}

// ------------------------- split conversion kernels -------------------------
__global__ void split_pair_r9(const float* __restrict__ X,
                              __nv_bfloat16* __restrict__ Yh,
                              __nv_bfloat16* __restrict__ Yl, size_t n) {
    for (size_t i = (size_t)blockIdx.x * blockDim.x + threadIdx.x; i < n;
         i += (size_t)gridDim.x * blockDim.x) {
        __nv_bfloat16 hi, lo; split2(X[i], hi, lo);
        Yh[i] = hi; Yl[i] = lo;
    }
}
// W[K][N] -> Th/Tl [N][K]
__global__ void tsplit_r9(const float* __restrict__ W,
                          __nv_bfloat16* __restrict__ Th, __nv_bfloat16* __restrict__ Tl,
                          int K, int N) {
    __shared__ float tile[32][33];
    int k0 = blockIdx.y * 32, n0 = blockIdx.x * 32;
    int tx = threadIdx.x, ty = threadIdx.y;
#pragma unroll
    for (int i = ty; i < 32; i += 8)
        tile[i][tx] = W[(size_t)(k0 + i) * N + n0 + tx];
    __syncthreads();
#pragma unroll
    for (int i = ty; i < 32; i += 8) {
        float v = tile[tx][i];
        __nv_bfloat16 h, l; split2(v, h, l);
        Th[(size_t)(n0 + i) * K + k0 + tx] = h;
        Tl[(size_t)(n0 + i) * K + k0 + tx] = l;
    }
}

// --------------------------- split-bf16 GEMM --------------------------------
// C = A'[M][K3] * B'[K3][N] + bias. A segments {hi,hi,lo}, B segments {hi,lo,hi}
// over logical K=2048. 128x128x32 tiles, 256 threads.
// mode: 0 = f32 out; 1 = Q (scale 0.125 + split); 2 = V (split); 3 = K (split + transpose)
#define GBM 128
#define GBN 128
#define GBK 32
#define ASTR 40
#define BSTR 136

__global__ __launch_bounds__(256) void gemm3_r9(
    const __nv_bfloat16* __restrict__ Ahi, const __nv_bfloat16* __restrict__ Alo,
    const __nv_bfloat16* __restrict__ Bhi, const __nv_bfloat16* __restrict__ Blo,
    const float* __restrict__ bias,
    __nv_bfloat16* __restrict__ Chi, __nv_bfloat16* __restrict__ Clo,
    float* __restrict__ Cf, int N, int mode)
{
    __shared__ __nv_bfloat16 As[2][GBM * ASTR];
    __shared__ __nv_bfloat16 Bs[2][GBK * BSTR];

    const int tid = threadIdx.x, lane = tid & 31, wid = tid >> 5;
    const int wm = wid >> 2, wn = wid & 3;
    const int rowBase = blockIdx.y * GBM, colBase = blockIdx.x * GBN;

    float acc[4][4][4];
#pragma unroll
    for (int a = 0; a < 4; a++)
#pragma unroll
        for (int b = 0; b < 4; b++)
#pragma unroll
            for (int c = 0; c < 4; c++) acc[a][b][c] = 0.f;

    auto loadTiles = [&](int s, int kt) {
        const int seg = kt >> 11, koff = kt & 2047;
        const __nv_bfloat16* Ab = (seg < 2) ? Ahi : Alo;
        const __nv_bfloat16* Bb = (seg == 1) ? Blo : Bhi;
#pragma unroll
        for (int h = 0; h < 2; h++) {
            int c = tid + h * 256;
            cp16(&As[s][(c >> 2) * ASTR + (c & 3) * 8],
                 &Ab[(size_t)(rowBase + (c >> 2)) * D_MODEL + koff + (c & 3) * 8]);
        }
#pragma unroll
        for (int h = 0; h < 2; h++) {
            int c = tid + h * 256;
            cp16(&Bs[s][(c >> 4) * BSTR + (c & 15) * 8],
                 &Bb[(size_t)(koff + (c >> 4)) * N + colBase + (c & 15) * 8]);
        }
    };

    const int niter = K3 / GBK;
    loadTiles(0, 0); cp_commit();

    for (int t = 0; t < niter; t++) {
        const int cur = t & 1;
        if (t + 1 < niter) { loadTiles(1 - cur, (t + 1) * GBK); cp_commit(); cp_wait<1>(); }
        else cp_wait<0>();
        __syncthreads();

        const __nv_bfloat16* Ab = As[cur];
        const __nv_bfloat16* Bb = Bs[cur];
#pragma unroll
        for (int kk = 0; kk < GBK; kk += 16) {
            uint32_t af[4][4], bf[2][4];
#pragma unroll
            for (int mi = 0; mi < 4; mi++)
                ldmA(af[mi], sptr(&Ab[(wm * 64 + mi * 16 + (lane & 15)) * ASTR
                                      + kk + 8 * (lane >> 4)]));
#pragma unroll
            for (int j = 0; j < 2; j++)
                ldmBT(bf[j], sptr(&Bb[(kk + (lane & 15)) * BSTR
                                      + wn * 32 + j * 16 + 8 * (lane >> 4)]));
#pragma unroll
            for (int mi = 0; mi < 4; mi++)
#pragma unroll
                for (int nj = 0; nj < 4; nj++)
                    mma16816(acc[mi][nj], af[mi], &bf[nj >> 1][(nj & 1) * 2]);
        }
        __syncthreads();
    }

#pragma unroll
    for (int mi = 0; mi < 4; mi++) {
        int row0 = rowBase + wm * 64 + mi * 16 + (lane >> 2);
#pragma unroll
        for (int nj = 0; nj < 4; nj++) {
            int col = colBase + wn * 32 + nj * 8 + 2 * (lane & 3);
            float bx = bias[col], by = bias[col + 1];
            float v00 = acc[mi][nj][0] + bx, v01 = acc[mi][nj][1] + by;
            float v10 = acc[mi][nj][2] + bx, v11 = acc[mi][nj][3] + by;
            if (mode == 0) {
                *reinterpret_cast<float2*>(Cf + (size_t)row0 * N + col) = make_float2(v00, v01);
                *reinterpret_cast<float2*>(Cf + (size_t)(row0 + 8) * N + col) = make_float2(v10, v11);
            } else {
                if (mode == 1) { v00 *= 0.125f; v01 *= 0.125f; v10 *= 0.125f; v11 *= 0.125f; }
                __nv_bfloat16 h00, l00, h01, l01, h10, l10, h11, l11;
                split2(v00, h00, l00); split2(v01, h01, l01);
                split2(v10, h10, l10); split2(v11, h11, l11);
                if (mode == 3) {
                    // K: scatter transposed [bg][d][t]
                    int b = row0 >> 11, t = row0 & 2047;
                    int g = col >> 6,  d = col & 63;
                    size_t base0 = ((size_t)(b * 8 + g) * 64 + d) * SEQ;
                    size_t base1 = base0 + SEQ;          // d+1 (col+1, same g: col even, d<63)
                    Chi[base0 + t] = h00;       Clo[base0 + t] = l00;
                    Chi[base1 + t] = h01;       Clo[base1 + t] = l01;
                    Chi[base0 + t + 8] = h10;   Clo[base0 + t + 8] = l10;
                    Chi[base1 + t + 8] = h11;   Clo[base1 + t + 8] = l11;
                } else {
                    *reinterpret_cast<__nv_bfloat162*>(Chi + (size_t)row0 * N + col) = mk2(h00, h01);
                    *reinterpret_cast<__nv_bfloat162*>(Clo + (size_t)row0 * N + col) = mk2(l00, l01);
                    *reinterpret_cast<__nv_bfloat162*>(Chi + (size_t)(row0 + 8) * N + col) = mk2(h10, h11);
                    *reinterpret_cast<__nv_bfloat162*>(Clo + (size_t)(row0 + 8) * N + col) = mk2(l10, l11);
                }
            }
        }
    }
}

// ----------------------- flash attention (2 heads / CTA) --------------------
#define FSTR 72
#define SSTR 68

__global__ __launch_bounds__(512) void gqa_flash_mma_r9(
    const __nv_bfloat16* __restrict__ Qh, const __nv_bfloat16* __restrict__ Ql,
    const __nv_bfloat16* __restrict__ KhT, const __nv_bfloat16* __restrict__ KlT,
    const __nv_bfloat16* __restrict__ Vh, const __nv_bfloat16* __restrict__ Vl,
    __nv_bfloat16* __restrict__ AOh, __nv_bfloat16* __restrict__ AOl)
{
    extern __shared__ char smraw[];
    __nv_bfloat16* Qhi = (__nv_bfloat16*)smraw;            // [128][FSTR]
    __nv_bfloat16* Qlo = Qhi + 128 * FSTR;
    __nv_bfloat16* Khi = Qlo + 128 * FSTR;                 // [2][64][FSTR] stages
    __nv_bfloat16* Klo = Khi + 2 * 64 * FSTR;
    __nv_bfloat16* Vhi = Klo + 2 * 64 * FSTR;
    __nv_bfloat16* Vlo = Vhi + 2 * 64 * FSTR;
    __nv_bfloat16* Phi = Vlo + 2 * 64 * FSTR;              // [128][FSTR]
    __nv_bfloat16* Plo = Phi + 128 * FSTR;
    float* Sf  = (float*)(Plo + 128 * FSTR);               // [128][SSTR]
    float* m_s = Sf + 128 * SSTR;
    float* l_s = m_s + 128;
    float* c_s = l_s + 128;

    const int tid = threadIdx.x, lane = tid & 31, wid = tid >> 5;
    const int wm = wid & 7, wn = wid >> 3;                 // 8 row groups x 2 col groups
    const int qblk = blockIdx.x, hp = blockIdx.y, b = blockIdx.z;
    const int g = hp >> 1;
    const size_t bg = (size_t)(b * 8 + g);
    const int g64 = g * 64;

    auto loadKV = [&](int st, int jb) {
        const int c = tid;                                 // 512 chunks per array
        const int r = c >> 3, off8 = (c & 7) * 8;
        size_t ksrc = (bg * 64 + r) * (size_t)SEQ + jb * 64 + off8;
        size_t vsrc = ((size_t)(b * SEQ + jb * 64 + r)) * KV_DIM + g64 + off8;
        cp16(Khi + st * 64 * FSTR + r * FSTR + off8, KhT + ksrc);
        cp16(Klo + st * 64 * FSTR + r * FSTR + off8, KlT + ksrc);
        cp16(Vhi + st * 64 * FSTR + r * FSTR + off8, Vh + vsrc);
        cp16(Vlo + st * 64 * FSTR + r * FSTR + off8, Vl + vsrc);
    };

    // prologue: KV stage 0, then Q
    loadKV(0, 0); cp_commit();
#pragma unroll
    for (int h = 0; h < 2; h++) {
        int c = tid + h * 512;                             // 1024 chunks
        int r = c >> 3, off8 = (c & 7) * 8;
        size_t src = ((size_t)(b * SEQ + qblk * 64 + (r & 63))) * D_MODEL
                   + (hp * 2 + (r >> 6)) * 64 + off8;
        cp16(Qhi + r * FSTR + off8, Qh + src);
        cp16(Qlo + r * FSTR + off8, Ql + src);
    }
    cp_commit();

    if (tid < 128) { m_s[tid] = -1e30f; l_s[tid] = 0.f; }

    float o[4][4];
#pragma unroll
    for (int i = 0; i < 4; i++)
#pragma unroll
        for (int j = 0; j < 4; j++) o[i][j] = 0.f;

    const int rowa = wm * 16 + (lane >> 2);
    const uint32_t aoff = 8 * (lane >> 4);
    const int arow15 = lane & 15;

    for (int jb = 0; jb < SEQ / 64; jb++) {
        const int cur = jb & 1;
        if (jb + 1 < SEQ / 64) { loadKV(1 - cur, jb + 1); cp_commit(); cp_wait<1>(); }
        else cp_wait<0>();
        __syncthreads();

        const __nv_bfloat16* Kc_h = Khi + cur * 64 * FSTR;
        const __nv_bfloat16* Kc_l = Klo + cur * 64 * FSTR;
        const __nv_bfloat16* Vc_h = Vhi + cur * 64 * FSTR;
        const __nv_bfloat16* Vc_l = Vlo + cur * 64 * FSTR;

        float s[4][4];
#pragma unroll
        for (int i = 0; i < 4; i++)
#pragma unroll
            for (int j = 0; j < 4; j++) s[i][j] = 0.f;

#pragma unroll
        for (int p = 0; p < 3; p++) {
            const __nv_bfloat16* Aseg = (p == 2) ? Qlo : Qhi;
            const __nv_bfloat16* Bseg = (p == 1) ? Kc_l : Kc_h;
#pragma unroll
            for (int kk = 0; kk < 64; kk += 16) {
                uint32_t af[4], bf[2][4];
                ldmA(af, sptr(&Aseg[(wm * 16 + arow15) * FSTR + kk + aoff]));
#pragma unroll
                for (int j = 0; j < 2; j++)
                    ldmBT(bf[j], sptr(&Bseg[(kk + arow15) * FSTR + wn * 32 + j * 16 + aoff]));
#pragma unroll
                for (int nj = 0; nj < 4; nj++)
                    mma16816(s[nj], af, &bf[nj >> 1][(nj & 1) * 2]);
            }
        }
#pragma unroll
        for (int nj = 0; nj < 4; nj++) {
            int col = wn * 32 + nj * 8 + 2 * (lane & 3);
            *reinterpret_cast<float2*>(&Sf[rowa * SSTR + col]) = make_float2(s[nj][0], s[nj][1]);
            *reinterpret_cast<float2*>(&Sf[(rowa + 8) * SSTR + col]) = make_float2(s[nj][2], s[nj][3]);
        }
        __syncthreads();

        // online softmax: 4 threads per row
        {
            int r = tid >> 2, i = tid & 3;
            float* srow = &Sf[r * SSTR + i * 16];
            float mold = m_s[r];
            float pm = -1e30f;
#pragma unroll
            for (int c = 0; c < 16; c++) pm = fmaxf(pm, srow[c]);
            pm = fmaxf(pm, __shfl_xor_sync(0xffffffffu, pm, 1));
            pm = fmaxf(pm, __shfl_xor_sync(0xffffffffu, pm, 2));
            float mx = fmaxf(mold, pm);
            float lsum = 0.f;
#pragma unroll
            for (int c = 0; c < 16; c++) {
                float p = __expf(srow[c] - mx);
                srow[c] = p; lsum += p;
            }
            lsum += __shfl_xor_sync(0xffffffffu, lsum, 1);
            lsum += __shfl_xor_sync(0xffffffffu, lsum, 2);
            if (i == 0) {
                float corr = __expf(mold - mx);
                l_s[r] = l_s[r] * corr + lsum;
                m_s[r] = mx;
                c_s[r] = corr;
            }
        }
        __syncthreads();

        // split P
        for (int idx = tid; idx < 128 * 64; idx += 512) {
            int r = idx >> 6, t = idx & 63;
            split2(Sf[r * SSTR + t], Phi[r * FSTR + t], Plo[r * FSTR + t]);
        }
        __syncthreads();

        // O = O*corr + P @ V (3-pass)
        {
            float cr0 = c_s[rowa], cr1 = c_s[rowa + 8];
#pragma unroll
            for (int nj = 0; nj < 4; nj++) {
                o[nj][0] *= cr0; o[nj][1] *= cr0;
                o[nj][2] *= cr1; o[nj][3] *= cr1;
            }
        }
#pragma unroll
        for (int p = 0; p < 3; p++) {
            const __nv_bfloat16* Aseg = (p == 2) ? Plo : Phi;
            const __nv_bfloat16* Bseg = (p == 1) ? Vc_l : Vc_h;
#pragma unroll
            for (int kk = 0; kk < 64; kk += 16) {
                uint32_t af[4], bf[2][4];
                ldmA(af, sptr(&Aseg[(wm * 16 + arow15) * FSTR + kk + aoff]));
#pragma unroll
                for (int j = 0; j < 2; j++)
                    ldmBT(bf[j], sptr(&Bseg[(kk + arow15) * FSTR + wn * 32 + j * 16 + aoff]));
#pragma unroll
                for (int nj = 0; nj < 4; nj++)
                    mma16816(o[nj], af, &bf[nj >> 1][(nj & 1) * 2]);
            }
        }
        __syncthreads();
    }

    // epilogue: normalize + split-write AO
    float il0 = 1.f / l_s[rowa], il1 = 1.f / l_s[rowa + 8];
    int head = hp * 2 + (rowa >> 6);
    size_t m0 = (size_t)(b * SEQ + qblk * 64 + (rowa & 63));
#pragma unroll
    for (int nj = 0; nj < 4; nj++) {
        int col = head * 64 + wn * 32 + nj * 8 + 2 * (lane & 3);
        float v00 = o[nj][0] * il0, v01 = o[nj][1] * il0;
        float v10 = o[nj][2] * il1, v11 = o[nj][3] * il1;
        __nv_bfloat16 h00, l00, h01, l01, h10, l10, h11, l11;
        split2(v00, h00, l00); split2(v01, h01, l01);
        split2(v10, h10, l10); split2(v11, h11, l11);
        *reinterpret_cast<__nv_bfloat162*>(AOh + m0 * D_MODEL + col) = mk2(h00, h01);
        *reinterpret_cast<__nv_bfloat162*>(AOl + m0 * D_MODEL + col) = mk2(l00, l01);
        *reinterpret_cast<__nv_bfloat162*>(AOh + (m0 + 8) * D_MODEL + col) = mk2(h10, h11);
        *reinterpret_cast<__nv_bfloat162*>(AOl + (m0 + 8) * D_MODEL + col) = mk2(l10, l11);
    }
}

// -----------------------------------------------------------------------------
extern "C" void kernel_launch(void* const* d_in, const int* in_sizes, int n_in,
                              void* d_out, int out_size)
{
    (void)in_sizes; (void)n_in; (void)out_size;
    const float* q  = (const float*)d_in[0];
    const float* k  = (const float*)d_in[1];
    const float* v  = (const float*)d_in[2];
    const float* Wq = (const float*)d_in[3];
    const float* bq = (const float*)d_in[4];
    const float* Wk = (const float*)d_in[5];
    const float* bk = (const float*)d_in[6];
    const float* Wv = (const float*)d_in[7];
    const float* bv = (const float*)d_in[8];
    const float* Wo = (const float*)d_in[9];
    const float* bo = (const float*)d_in[10];
    float* out = (float*)d_out;

    __nv_bfloat16 *qih,*qil,*kih,*kil,*vih,*vil;
    __nv_bfloat16 *wqh,*wql,*wkh,*wkl,*wvh,*wvl,*woh,*wol;
    __nv_bfloat16 *Qh,*Ql,*KhT,*KlT,*Vh,*Vl,*AOh,*AOl;
    cudaGetSymbolAddress((void**)&qih, s_qih); cudaGetSymbolAddress((void**)&qil, s_qil);
    cudaGetSymbolAddress((void**)&kih, s_kih); cudaGetSymbolAddress((void**)&kil, s_kil);
    cudaGetSymbolAddress((void**)&vih, s_vih); cudaGetSymbolAddress((void**)&vil, s_vil);
    cudaGetSymbolAddress((void**)&wqh, s_wqh); cudaGetSymbolAddress((void**)&wql, s_wql);
    cudaGetSymbolAddress((void**)&wkh, s_wkh); cudaGetSymbolAddress((void**)&wkl, s_wkl);
    cudaGetSymbolAddress((void**)&wvh, s_wvh); cudaGetSymbolAddress((void**)&wvl, s_wvl);
    cudaGetSymbolAddress((void**)&woh, s_woh); cudaGetSymbolAddress((void**)&wol, s_wol);
    cudaGetSymbolAddress((void**)&Qh,  g_Qh);  cudaGetSymbolAddress((void**)&Ql,  g_Ql);
    cudaGetSymbolAddress((void**)&KhT, g_KhT); cudaGetSymbolAddress((void**)&KlT, g_KlT);
    cudaGetSymbolAddress((void**)&Vh,  g_Vh);  cudaGetSymbolAddress((void**)&Vl,  g_Vl);
    cudaGetSymbolAddress((void**)&AOh, g_AOh); cudaGetSymbolAddress((void**)&AOl, g_AOl);

    const size_t flash_smem =
        (2 * 128 * FSTR + 4 * 2 * 64 * FSTR + 2 * 128 * FSTR) * sizeof(__nv_bfloat16)
        + (128 * SSTR + 3 * 128) * sizeof(float);
    cudaFuncSetAttribute(gqa_flash_mma_r9, cudaFuncAttributeMaxDynamicSharedMemorySize,
                         (int)flash_smem);

    // splits (hi/lo pairs only)
    const size_t nMD = (size_t)M_TOT * D_MODEL;
    const size_t nDD = (size_t)D_MODEL * D_MODEL;
    const size_t nDK = (size_t)D_MODEL * KV_DIM;
    split_pair_r9<<<2048, 256>>>(q, qih, qil, nMD);
    split_pair_r9<<<2048, 256>>>(k, kih, kil, nMD);
    split_pair_r9<<<2048, 256>>>(v, vih, vil, nMD);
    split_pair_r9<<<2048, 256>>>(Wq, wqh, wql, nDD);
    split_pair_r9<<<512,  256>>>(Wk, wkh, wkl, nDK);
    split_pair_r9<<<512,  256>>>(Wv, wvh, wvl, nDK);
    split_pair_r9<<<2048, 256>>>(Wo, woh, wol, nDD);

    // projections with fused split epilogues
    gemm3_r9<<<dim3(D_MODEL / GBN, M_TOT / GBM), 256>>>(qih, qil, wqh, wql, bq,
        Qh, Ql, nullptr, D_MODEL, 1);
    gemm3_r9<<<dim3(KV_DIM / GBN, M_TOT / GBM), 256>>>(kih, kil, wkh, wkl, bk,
        KhT, KlT, nullptr, KV_DIM, 3);
    gemm3_r9<<<dim3(KV_DIM / GBN, M_TOT / GBM), 256>>>(vih, vil, wvh, wvl, bv,
        Vh, Vl, nullptr, KV_DIM, 2);

    // attention (2 heads per CTA)
    gqa_flash_mma_r9<<<dim3(SEQ / 64, NUM_HEADS / 2, BATCH), 512, flash_smem>>>(
        Qh, Ql, KhT, KlT, Vh, Vl, AOh, AOl);

    // output projection
    gemm3_r9<<<dim3(D_MODEL / GBN, M_TOT / GBM), 256>>>(AOh, AOl, woh, wol, bo,
        nullptr, nullptr, out, D_MODEL, 0);
}

// round 11
// speedup vs baseline: 2.1808x; 1.8385x over previous
#include <cuda_runtime.h>
#include <cuda_bf16.h>
#include <math.h>
#include <stdint.h>

#define D_MODEL   2048
#define KV_DIM    512
#define HEAD_DIM  64
#define NUM_HEADS 32
#define BATCH     2
#define SEQ       2048
#define M_TOT     (BATCH*SEQ)   // 4096
#define K3        (3*D_MODEL)   // 6144 (3-pass split-K)

// ---------------- scratch (__device__ globals; no allocation) ---------------
__device__ __nv_bfloat16 s_qih[(size_t)M_TOT * D_MODEL];
__device__ __nv_bfloat16 s_qil[(size_t)M_TOT * D_MODEL];
__device__ __nv_bfloat16 s_kih[(size_t)M_TOT * D_MODEL];
__device__ __nv_bfloat16 s_kil[(size_t)M_TOT * D_MODEL];
__device__ __nv_bfloat16 s_vih[(size_t)M_TOT * D_MODEL];
__device__ __nv_bfloat16 s_vil[(size_t)M_TOT * D_MODEL];
// weights kept [K][N] hi/lo — matches gemm3's B loader (validated R3/R9 path)
__device__ __nv_bfloat16 s_wqh[(size_t)D_MODEL * D_MODEL];
__device__ __nv_bfloat16 s_wql[(size_t)D_MODEL * D_MODEL];
__device__ __nv_bfloat16 s_wkh[(size_t)D_MODEL * KV_DIM];
__device__ __nv_bfloat16 s_wkl[(size_t)D_MODEL * KV_DIM];
__device__ __nv_bfloat16 s_wvh[(size_t)D_MODEL * KV_DIM];
__device__ __nv_bfloat16 s_wvl[(size_t)D_MODEL * KV_DIM];
__device__ __nv_bfloat16 s_woh[(size_t)D_MODEL * D_MODEL];
__device__ __nv_bfloat16 s_wol[(size_t)D_MODEL * D_MODEL];
__device__ __nv_bfloat16 g_Qh[(size_t)M_TOT * D_MODEL];           // pre-scaled
__device__ __nv_bfloat16 g_Ql[(size_t)M_TOT * D_MODEL];
__device__ __nv_bfloat16 g_KhT[(size_t)16 * HEAD_DIM * SEQ];      // [bg][d][t]
__device__ __nv_bfloat16 g_KlT[(size_t)16 * HEAD_DIM * SEQ];
__device__ __nv_bfloat16 g_Vh [(size_t)M_TOT * KV_DIM];
__device__ __nv_bfloat16 g_Vl [(size_t)M_TOT * KV_DIM];
__device__ __nv_bfloat16 g_AOh[(size_t)M_TOT * D_MODEL];
__device__ __nv_bfloat16 g_AOl[(size_t)M_TOT * D_MODEL];

// ------------------------------ helpers -------------------------------------
__device__ __forceinline__ uint32_t sptr(const void* p) {
    return (uint32_t)__cvta_generic_to_shared(p);
}
__device__ __forceinline__ void cp16(void* dst, const void* src) {
    asm volatile("cp.async.cg.shared.global [%0], [%1], 16;"
                 :: "r"(sptr(dst)), "l"(src));
}
__device__ __forceinline__ void cp_commit() { asm volatile("cp.async.commit_group;"); }
template<int N_> __device__ __forceinline__ void cp_wait() {
    asm volatile("cp.async.wait_group %0;" :: "n"(N_));
}
__device__ __forceinline__ void ldmA(uint32_t* r, uint32_t a) {
    asm volatile("ldmatrix.sync.aligned.m8n8.x4.shared.b16 {%0,%1,%2,%3}, [%4];"
                 : "=r"(r[0]), "=r"(r[1]), "=r"(r[2]), "=r"(r[3]) : "r"(a));
}
__device__ __forceinline__ void ldmBT(uint32_t* r, uint32_t a) {
    asm volatile("ldmatrix.sync.aligned.m8n8.x4.trans.shared.b16 {%0,%1,%2,%3}, [%4];"
                 : "=r"(r[0]), "=r"(r[1]), "=r"(r[2]), "=r"(r[3]) : "r"(a));
}
__device__ __forceinline__ void mma16816(float* c, const uint32_t* a, const uint32_t* b) {
    asm volatile("mma.sync.aligned.m16n8k16.row.col.f32.bf16.bf16.f32 "
                 "{%0,%1,%2,%3}, {%4,%5,%6,%7}, {%8,%9}, {%0,%1,%2,%3};"
                 : "+f"(c[0]), "+f"(c[1]), "+f"(c[2]), "+f"(c[3])
                 : "r"(a[0]), "r"(a[1]), "r"(a[2]), "r"(a[3]), "r"(b[0]), "r"(b[1]));
}
__device__ __forceinline__ void split2(float x, __nv_bfloat16& hi, __nv_bfloat16& lo) {
    hi = __float2bfloat16(x);
    lo = __float2bfloat16(x - __bfloat162float(hi));
}
__device__ __forceinline__ __nv_bfloat162 mk2(__nv_bfloat16 a, __nv_bfloat16 b) {
    __nv_bfloat162 r; r.x = a; r.y = b; return r;
}
__device__ __forceinline__ uint32_t packbf(float a, float b) {
    __nv_bfloat162 t = mk2(__float2bfloat16(a), __float2bfloat16(b));
    return *reinterpret_cast<uint32_t*>(&t);
}

// ------------------------- split conversion kernels -------------------------
__global__ void split_pair_r10(const float* __restrict__ X,
                               __nv_bfloat16* __restrict__ Yh,
                               __nv_bfloat16* __restrict__ Yl, size_t n) {
    for (size_t i = (size_t)blockIdx.x * blockDim.x + threadIdx.x; i < n;
         i += (size_t)gridDim.x * blockDim.x) {
        __nv_bfloat16 hi, lo; split2(X[i], hi, lo);
        Yh[i] = hi; Yl[i] = lo;
    }
}

// --------------------------- split-bf16 GEMM --------------------------------
// C = A'[M][K3] * B'[K3][N] + bias. A segments {hi,hi,lo}, B segments {hi,lo,hi}.
// B consumed row-major [K][N] (matches split_pair prep). Single-sync pipeline.
#define GBM 128
#define GBN 128
#define GBK 32
#define ASTR 40
#define BSTR 136

__global__ __launch_bounds__(256, 2) void gemm3_r10(
    const __nv_bfloat16* __restrict__ Ahi, const __nv_bfloat16* __restrict__ Alo,
    const __nv_bfloat16* __restrict__ Bhi, const __nv_bfloat16* __restrict__ Blo,
    const float* __restrict__ bias,
    __nv_bfloat16* __restrict__ Chi, __nv_bfloat16* __restrict__ Clo,
    float* __restrict__ Cf, int N, int mode)
{
    __shared__ __nv_bfloat16 As[2][GBM * ASTR];
    __shared__ __nv_bfloat16 Bs[2][GBK * BSTR];

    const int tid = threadIdx.x, lane = tid & 31, wid = tid >> 5;
    const int wm = wid >> 2, wn = wid & 3;
    const int rowBase = blockIdx.y * GBM, colBase = blockIdx.x * GBN;

    float acc[4][4][4];
#pragma unroll
    for (int a = 0; a < 4; a++)
#pragma unroll
        for (int b = 0; b < 4; b++)
#pragma unroll
            for (int c = 0; c < 4; c++) acc[a][b][c] = 0.f;

    auto loadTiles = [&](int s, int kt) {
        const int seg = kt >> 11, koff = kt & 2047;
        const __nv_bfloat16* Ab = (seg < 2) ? Ahi : Alo;
        const __nv_bfloat16* Bb = (seg == 1) ? Blo : Bhi;
#pragma unroll
        for (int h = 0; h < 2; h++) {
            int c = tid + h * 256;
            cp16(&As[s][(c >> 2) * ASTR + (c & 3) * 8],
                 &Ab[(size_t)(rowBase + (c >> 2)) * D_MODEL + koff + (c & 3) * 8]);
        }
#pragma unroll
        for (int h = 0; h < 2; h++) {
            int c = tid + h * 256;
            cp16(&Bs[s][(c >> 4) * BSTR + (c & 15) * 8],
                 &Bb[(size_t)(koff + (c >> 4)) * N + colBase + (c & 15) * 8]);
        }
    };

    const int niter = K3 / GBK;
    loadTiles(0, 0); cp_commit();

    for (int t = 0; t < niter; t++) {
        const int cur = t & 1;
        cp_wait<0>();
        __syncthreads();                 // stage cur arrived; all warps done reading 1-cur
        if (t + 1 < niter) { loadTiles(1 - cur, (t + 1) * GBK); cp_commit(); }

        const __nv_bfloat16* Ab = As[cur];
        const __nv_bfloat16* Bb = Bs[cur];
#pragma unroll
        for (int kk = 0; kk < GBK; kk += 16) {
            uint32_t af[4][4], bf[2][4];
#pragma unroll
            for (int mi = 0; mi < 4; mi++)
                ldmA(af[mi], sptr(&Ab[(wm * 64 + mi * 16 + (lane & 15)) * ASTR
                                      + kk + 8 * (lane >> 4)]));
#pragma unroll
            for (int j = 0; j < 2; j++)
                ldmBT(bf[j], sptr(&Bb[(kk + (lane & 15)) * BSTR
                                      + wn * 32 + j * 16 + 8 * (lane >> 4)]));
#pragma unroll
            for (int mi = 0; mi < 4; mi++)
#pragma unroll
                for (int nj = 0; nj < 4; nj++)
                    mma16816(acc[mi][nj], af[mi], &bf[nj >> 1][(nj & 1) * 2]);
        }
    }

#pragma unroll
    for (int mi = 0; mi < 4; mi++) {
        int row0 = rowBase + wm * 64 + mi * 16 + (lane >> 2);
#pragma unroll
        for (int nj = 0; nj < 4; nj++) {
            int col = colBase + wn * 32 + nj * 8 + 2 * (lane & 3);
            float bx = bias[col], by = bias[col + 1];
            float v00 = acc[mi][nj][0] + bx, v01 = acc[mi][nj][1] + by;
            float v10 = acc[mi][nj][2] + bx, v11 = acc[mi][nj][3] + by;
            if (mode == 0) {
                *reinterpret_cast<float2*>(Cf + (size_t)row0 * N + col) = make_float2(v00, v01);
                *reinterpret_cast<float2*>(Cf + (size_t)(row0 + 8) * N + col) = make_float2(v10, v11);
            } else {
                if (mode == 1) { v00 *= 0.125f; v01 *= 0.125f; v10 *= 0.125f; v11 *= 0.125f; }
                __nv_bfloat16 h00, l00, h01, l01, h10, l10, h11, l11;
                split2(v00, h00, l00); split2(v01, h01, l01);
                split2(v10, h10, l10); split2(v11, h11, l11);
                if (mode == 3) {
                    int b = row0 >> 11, t = row0 & 2047;
                    int g = col >> 6,  d = col & 63;
                    size_t base0 = ((size_t)(b * 8 + g) * 64 + d) * SEQ;
                    size_t base1 = base0 + SEQ;
                    Chi[base0 + t] = h00;       Clo[base0 + t] = l00;
                    Chi[base1 + t] = h01;       Clo[base1 + t] = l01;
                    Chi[base0 + t + 8] = h10;   Clo[base0 + t + 8] = l10;
                    Chi[base1 + t + 8] = h11;   Clo[base1 + t + 8] = l11;
                } else {
                    *reinterpret_cast<__nv_bfloat162*>(Chi + (size_t)row0 * N + col) = mk2(h00, h01);
                    *reinterpret_cast<__nv_bfloat162*>(Clo + (size_t)row0 * N + col) = mk2(l00, l01);
                    *reinterpret_cast<__nv_bfloat162*>(Chi + (size_t)(row0 + 8) * N + col) = mk2(h10, h11);
                    *reinterpret_cast<__nv_bfloat162*>(Clo + (size_t)(row0 + 8) * N + col) = mk2(l10, l11);
                }
            }
        }
    }
}

// ---------------- flash attention: register softmax, 2 heads / CTA ----------
// 256 threads, 8 warps; warp = 16 q-rows x full 64 kv-cols. S and P in registers.
#define FSTR 72

__global__ __launch_bounds__(256) void gqa_flash_mma_r10(
    const __nv_bfloat16* __restrict__ Qh, const __nv_bfloat16* __restrict__ Ql,
    const __nv_bfloat16* __restrict__ KhT, const __nv_bfloat16* __restrict__ KlT,
    const __nv_bfloat16* __restrict__ Vh, const __nv_bfloat16* __restrict__ Vl,
    __nv_bfloat16* __restrict__ AOh, __nv_bfloat16* __restrict__ AOl)
{
    extern __shared__ char smraw[];
    __nv_bfloat16* Qhi = (__nv_bfloat16*)smraw;            // [128][FSTR]
    __nv_bfloat16* Qlo = Qhi + 128 * FSTR;
    __nv_bfloat16* Khi = Qlo + 128 * FSTR;                 // [2][64][FSTR]
    __nv_bfloat16* Klo = Khi + 2 * 64 * FSTR;
    __nv_bfloat16* Vhi = Klo + 2 * 64 * FSTR;
    __nv_bfloat16* Vlo = Vhi + 2 * 64 * FSTR;

    const int tid = threadIdx.x, lane = tid & 31, wid = tid >> 5;
    const int grp = lane >> 2, tq = lane & 3;
    const int qblk = blockIdx.x, hp = blockIdx.y, b = blockIdx.z;
    const int g = hp >> 1;
    const size_t bg = (size_t)(b * 8 + g);
    const int g64 = g * 64;

    auto loadKV = [&](int st, int jb) {
#pragma unroll
        for (int h = 0; h < 2; h++) {
            int c = tid + h * 256;                         // 512 chunks / array
            int r = c >> 3, off8 = (c & 7) * 8;
            size_t ksrc = (bg * 64 + r) * (size_t)SEQ + jb * 64 + off8;
            size_t vsrc = ((size_t)(b * SEQ + jb * 64 + r)) * KV_DIM + g64 + off8;
            cp16(Khi + st * 64 * FSTR + r * FSTR + off8, KhT + ksrc);
            cp16(Klo + st * 64 * FSTR + r * FSTR + off8, KlT + ksrc);
            cp16(Vhi + st * 64 * FSTR + r * FSTR + off8, Vh + vsrc);
            cp16(Vlo + st * 64 * FSTR + r * FSTR + off8, Vl + vsrc);
        }
    };

    loadKV(0, 0); cp_commit();
#pragma unroll
    for (int h = 0; h < 4; h++) {
        int c = tid + h * 256;                             // 1024 chunks
        int r = c >> 3, off8 = (c & 7) * 8;
        size_t src = ((size_t)(b * SEQ + qblk * 64 + (r & 63))) * D_MODEL
                   + (hp * 2 + (r >> 6)) * 64 + off8;
        cp16(Qhi + r * FSTR + off8, Qh + src);
        cp16(Qlo + r * FSTR + off8, Ql + src);
    }
    cp_commit();

    float m0 = -1e30f, m1 = -1e30f, l0 = 0.f, l1 = 0.f;
    float o[8][4];
#pragma unroll
    for (int i = 0; i < 8; i++)
#pragma unroll
        for (int j = 0; j < 4; j++) o[i][j] = 0.f;

    const uint32_t arow = (wid * 16 + (lane & 15)) * FSTR + 8 * (lane >> 4);
    const uint32_t brow = (lane & 15) * FSTR + 8 * (lane >> 4);

    for (int jb = 0; jb < SEQ / 64; jb++) {
        const int cur = jb & 1;
        cp_wait<0>();
        __syncthreads();
        if (jb + 1 < SEQ / 64) { loadKV(1 - cur, jb + 1); cp_commit(); }

        const __nv_bfloat16* Kc_h = Khi + cur * 64 * FSTR;
        const __nv_bfloat16* Kc_l = Klo + cur * 64 * FSTR;
        const __nv_bfloat16* Vc_h = Vhi + cur * 64 * FSTR;
        const __nv_bfloat16* Vc_l = Vlo + cur * 64 * FSTR;

        // ---- S = Q @ K^T (3-pass split) ----
        float s[8][4];
#pragma unroll
        for (int i = 0; i < 8; i++)
#pragma unroll
            for (int j = 0; j < 4; j++) s[i][j] = 0.f;

#pragma unroll
        for (int p = 0; p < 3; p++) {
            const __nv_bfloat16* Aseg = (p == 2) ? Qlo : Qhi;
            const __nv_bfloat16* Bseg = (p == 1) ? Kc_l : Kc_h;
#pragma unroll
            for (int kk = 0; kk < 4; kk++) {
                uint32_t af[4], bf[4][4];
                ldmA(af, sptr(Aseg + kk * 16 + arow));
#pragma unroll
                for (int j = 0; j < 4; j++)
                    ldmBT(bf[j], sptr(Bseg + kk * 16 * FSTR + j * 16 + brow));
#pragma unroll
                for (int nj = 0; nj < 8; nj++)
                    mma16816(s[nj], af, &bf[nj >> 1][(nj & 1) * 2]);
            }
        }

        // ---- online softmax in registers ----
        float pm0 = -1e30f, pm1 = -1e30f;
#pragma unroll
        for (int nj = 0; nj < 8; nj++) {
            pm0 = fmaxf(pm0, fmaxf(s[nj][0], s[nj][1]));
            pm1 = fmaxf(pm1, fmaxf(s[nj][2], s[nj][3]));
        }
        pm0 = fmaxf(pm0, __shfl_xor_sync(~0u, pm0, 1));
        pm0 = fmaxf(pm0, __shfl_xor_sync(~0u, pm0, 2));
        pm1 = fmaxf(pm1, __shfl_xor_sync(~0u, pm1, 1));
        pm1 = fmaxf(pm1, __shfl_xor_sync(~0u, pm1, 2));
        float mn0 = fmaxf(m0, pm0), mn1 = fmaxf(m1, pm1);
        float corr0 = __expf(m0 - mn0), corr1 = __expf(m1 - mn1);
        m0 = mn0; m1 = mn1;

        float ls0 = 0.f, ls1 = 0.f;
        uint32_t pHi[4][4], pLo[4][4];
#pragma unroll
        for (int nj = 0; nj < 8; nj++) {
            float p0 = __expf(s[nj][0] - mn0);
            float p1 = __expf(s[nj][1] - mn0);
            float p2 = __expf(s[nj][2] - mn1);
            float p3 = __expf(s[nj][3] - mn1);
            ls0 += p0 + p1; ls1 += p2 + p3;
            const int kk = nj >> 1, hf = (nj & 1) * 2;
            uint32_t h01 = packbf(p0, p1), h23 = packbf(p2, p3);
            pHi[kk][hf]     = h01;
            pHi[kk][hf + 1] = h23;
            __nv_bfloat162 hh01 = *reinterpret_cast<__nv_bfloat162*>(&h01);
            __nv_bfloat162 hh23 = *reinterpret_cast<__nv_bfloat162*>(&h23);
            pLo[kk][hf]     = packbf(p0 - __bfloat162float(hh01.x),
                                     p1 - __bfloat162float(hh01.y));
            pLo[kk][hf + 1] = packbf(p2 - __bfloat162float(hh23.x),
                                     p3 - __bfloat162float(hh23.y));
        }
        ls0 += __shfl_xor_sync(~0u, ls0, 1); ls0 += __shfl_xor_sync(~0u, ls0, 2);
        ls1 += __shfl_xor_sync(~0u, ls1, 1); ls1 += __shfl_xor_sync(~0u, ls1, 2);
        l0 = l0 * corr0 + ls0;
        l1 = l1 * corr1 + ls1;
#pragma unroll
        for (int nj = 0; nj < 8; nj++) {
            o[nj][0] *= corr0; o[nj][1] *= corr0;
            o[nj][2] *= corr1; o[nj][3] *= corr1;
        }

        // ---- O += P @ V (3-pass split, P in registers) ----
#pragma unroll
        for (int p = 0; p < 3; p++) {
            const uint32_t (*Pa)[4] = (p == 2) ? pLo : pHi;
            const __nv_bfloat16* Bseg = (p == 1) ? Vc_l : Vc_h;
#pragma unroll
            for (int kk = 0; kk < 4; kk++) {
                uint32_t bf[4][4];
#pragma unroll
                for (int j = 0; j < 4; j++)
                    ldmBT(bf[j], sptr(Bseg + kk * 16 * FSTR + j * 16 + brow));
#pragma unroll
                for (int nj = 0; nj < 8; nj++)
                    mma16816(o[nj], Pa[kk], &bf[nj >> 1][(nj & 1) * 2]);
            }
        }
    }

    // ---- epilogue: normalize + split-write AO ----
    const int rowa = wid * 16 + grp;
    float il0 = 1.f / l0, il1 = 1.f / l1;
    int head = hp * 2 + (rowa >> 6);
    size_t m0r = (size_t)(b * SEQ + qblk * 64 + (rowa & 63));
#pragma unroll
    for (int nj = 0; nj < 8; nj++) {
        int col = head * 64 + nj * 8 + 2 * tq;
        float v00 = o[nj][0] * il0, v01 = o[nj][1] * il0;
        float v10 = o[nj][2] * il1, v11 = o[nj][3] * il1;
        __nv_bfloat16 h00, l00, h01, l01, h10, l10, h11, l11;
        split2(v00, h00, l00); split2(v01, h01, l01);
        split2(v10, h10, l10); split2(v11, h11, l11);
        *reinterpret_cast<__nv_bfloat162*>(AOh + m0r * D_MODEL + col) = mk2(h00, h01);
        *reinterpret_cast<__nv_bfloat162*>(AOl + m0r * D_MODEL + col) = mk2(l00, l01);
        *reinterpret_cast<__nv_bfloat162*>(AOh + (m0r + 8) * D_MODEL + col) = mk2(h10, h11);
        *reinterpret_cast<__nv_bfloat162*>(AOl + (m0r + 8) * D_MODEL + col) = mk2(l10, l11);
    }
}

// -----------------------------------------------------------------------------
extern "C" void kernel_launch(void* const* d_in, const int* in_sizes, int n_in,
                              void* d_out, int out_size)
{
    (void)in_sizes; (void)n_in; (void)out_size;
    const float* q  = (const float*)d_in[0];
    const float* k  = (const float*)d_in[1];
    const float* v  = (const float*)d_in[2];
    const float* Wq = (const float*)d_in[3];
    const float* bq = (const float*)d_in[4];
    const float* Wk = (const float*)d_in[5];
    const float* bk = (const float*)d_in[6];
    const float* Wv = (const float*)d_in[7];
    const float* bv = (const float*)d_in[8];
    const float* Wo = (const float*)d_in[9];
    const float* bo = (const float*)d_in[10];
    float* out = (float*)d_out;

    __nv_bfloat16 *qih,*qil,*kih,*kil,*vih,*vil;
    __nv_bfloat16 *wqh,*wql,*wkh,*wkl,*wvh,*wvl,*woh,*wol;
    __nv_bfloat16 *Qh,*Ql,*KhT,*KlT,*Vh,*Vl,*AOh,*AOl;
    cudaGetSymbolAddress((void**)&qih, s_qih); cudaGetSymbolAddress((void**)&qil, s_qil);
    cudaGetSymbolAddress((void**)&kih, s_kih); cudaGetSymbolAddress((void**)&kil, s_kil);
    cudaGetSymbolAddress((void**)&vih, s_vih); cudaGetSymbolAddress((void**)&vil, s_vil);
    cudaGetSymbolAddress((void**)&wqh, s_wqh); cudaGetSymbolAddress((void**)&wql, s_wql);
    cudaGetSymbolAddress((void**)&wkh, s_wkh); cudaGetSymbolAddress((void**)&wkl, s_wkl);
    cudaGetSymbolAddress((void**)&wvh, s_wvh); cudaGetSymbolAddress((void**)&wvl, s_wvl);
    cudaGetSymbolAddress((void**)&woh, s_woh); cudaGetSymbolAddress((void**)&wol, s_wol);
    cudaGetSymbolAddress((void**)&Qh,  g_Qh);  cudaGetSymbolAddress((void**)&Ql,  g_Ql);
    cudaGetSymbolAddress((void**)&KhT, g_KhT); cudaGetSymbolAddress((void**)&KlT, g_KlT);
    cudaGetSymbolAddress((void**)&Vh,  g_Vh);  cudaGetSymbolAddress((void**)&Vl,  g_Vl);
    cudaGetSymbolAddress((void**)&AOh, g_AOh); cudaGetSymbolAddress((void**)&AOl, g_AOl);

    const size_t flash_smem =
        (2 * 128 * FSTR + 4 * 2 * 64 * FSTR) * sizeof(__nv_bfloat16);   // 110592
    cudaFuncSetAttribute(gqa_flash_mma_r10, cudaFuncAttributeMaxDynamicSharedMemorySize,
                         (int)flash_smem);

    // splits (hi/lo pairs; weights stay [K][N] — matches gemm3 B loader)
    const size_t nMD = (size_t)M_TOT * D_MODEL;
    const size_t nDD = (size_t)D_MODEL * D_MODEL;
    const size_t nDK = (size_t)D_MODEL * KV_DIM;
    split_pair_r10<<<2048, 256>>>(q, qih, qil, nMD);
    split_pair_r10<<<2048, 256>>>(k, kih, kil, nMD);
    split_pair_r10<<<2048, 256>>>(v, vih, vil, nMD);
    split_pair_r10<<<2048, 256>>>(Wq, wqh, wql, nDD);
    split_pair_r10<<<512,  256>>>(Wk, wkh, wkl, nDK);
    split_pair_r10<<<512,  256>>>(Wv, wvh, wvl, nDK);
    split_pair_r10<<<2048, 256>>>(Wo, woh, wol, nDD);

    // projections with fused split epilogues
    gemm3_r10<<<dim3(D_MODEL / GBN, M_TOT / GBM), 256>>>(qih, qil, wqh, wql, bq,
        Qh, Ql, nullptr, D_MODEL, 1);
    gemm3_r10<<<dim3(KV_DIM / GBN, M_TOT / GBM), 256>>>(kih, kil, wkh, wkl, bk,
        KhT, KlT, nullptr, KV_DIM, 3);
    gemm3_r10<<<dim3(KV_DIM / GBN, M_TOT / GBM), 256>>>(vih, vil, wvh, wvl, bv,
        Vh, Vl, nullptr, KV_DIM, 2);

    // attention (register softmax, 2 heads per CTA)
    gqa_flash_mma_r10<<<dim3(SEQ / 64, NUM_HEADS / 2, BATCH), 256, flash_smem>>>(
        Qh, Ql, KhT, KlT, Vh, Vl, AOh, AOl);

    // output projection
    gemm3_r10<<<dim3(D_MODEL / GBN, M_TOT / GBM), 256>>>(AOh, AOl, woh, wol, bo,
        nullptr, nullptr, out, D_MODEL, 0);
}

// round 12
// speedup vs baseline: 3.1323x; 1.4363x over previous
#include <cuda_runtime.h>
#include <cuda_fp16.h>
#include <math.h>
#include <stdint.h>

#define D_MODEL   2048
#define KV_DIM    512
#define HEAD_DIM  64
#define NUM_HEADS 32
#define BATCH     2
#define SEQ       2048
#define M_TOT     (BATCH*SEQ)   // 4096
#define K2        (2*D_MODEL)   // 4096 (2-pass split-K: A={hi,lo} x Bh)

// ---------------- scratch (__device__ globals; no allocation) ---------------
__device__ __half s_qih[(size_t)M_TOT * D_MODEL];
__device__ __half s_qil[(size_t)M_TOT * D_MODEL];
__device__ __half s_kih[(size_t)M_TOT * D_MODEL];
__device__ __half s_kil[(size_t)M_TOT * D_MODEL];
__device__ __half s_vih[(size_t)M_TOT * D_MODEL];
__device__ __half s_vil[(size_t)M_TOT * D_MODEL];
// weights: fp16 hi only, [K][N] (B side of asymmetric split)
__device__ __half s_wqh[(size_t)D_MODEL * D_MODEL];
__device__ __half s_wkh[(size_t)D_MODEL * KV_DIM];
__device__ __half s_wvh[(size_t)D_MODEL * KV_DIM];
__device__ __half s_woh[(size_t)D_MODEL * D_MODEL];
// projected tensors
__device__ __half g_Qh[(size_t)M_TOT * D_MODEL];           // pre-scaled, hi
__device__ __half g_Ql[(size_t)M_TOT * D_MODEL];           // pre-scaled, lo
__device__ __half g_KhT[(size_t)16 * HEAD_DIM * SEQ];      // [bg][d][t], hi only
__device__ __half g_Vh [(size_t)M_TOT * KV_DIM];           // hi only
__device__ __half g_AOh[(size_t)M_TOT * D_MODEL];
__device__ __half g_AOl[(size_t)M_TOT * D_MODEL];

// ------------------------------ helpers -------------------------------------
__device__ __forceinline__ uint32_t sptr(const void* p) {
    return (uint32_t)__cvta_generic_to_shared(p);
}
__device__ __forceinline__ void cp16(void* dst, const void* src) {
    asm volatile("cp.async.cg.shared.global [%0], [%1], 16;"
                 :: "r"(sptr(dst)), "l"(src));
}
__device__ __forceinline__ void cp_commit() { asm volatile("cp.async.commit_group;"); }
template<int N_> __device__ __forceinline__ void cp_wait() {
    asm volatile("cp.async.wait_group %0;" :: "n"(N_));
}
__device__ __forceinline__ void ldmA(uint32_t* r, uint32_t a) {
    asm volatile("ldmatrix.sync.aligned.m8n8.x4.shared.b16 {%0,%1,%2,%3}, [%4];"
                 : "=r"(r[0]), "=r"(r[1]), "=r"(r[2]), "=r"(r[3]) : "r"(a));
}
__device__ __forceinline__ void ldmBT(uint32_t* r, uint32_t a) {
    asm volatile("ldmatrix.sync.aligned.m8n8.x4.trans.shared.b16 {%0,%1,%2,%3}, [%4];"
                 : "=r"(r[0]), "=r"(r[1]), "=r"(r[2]), "=r"(r[3]) : "r"(a));
}
__device__ __forceinline__ void mma16816h(float* c, const uint32_t* a, const uint32_t* b) {
    asm volatile("mma.sync.aligned.m16n8k16.row.col.f32.f16.f16.f32 "
                 "{%0,%1,%2,%3}, {%4,%5,%6,%7}, {%8,%9}, {%0,%1,%2,%3};"
                 : "+f"(c[0]), "+f"(c[1]), "+f"(c[2]), "+f"(c[3])
                 : "r"(a[0]), "r"(a[1]), "r"(a[2]), "r"(a[3]), "r"(b[0]), "r"(b[1]));
}
__device__ __forceinline__ void split2h(float x, __half& hi, __half& lo) {
    hi = __float2half_rn(x);
    lo = __float2half_rn(x - __half2float(hi));
}
__device__ __forceinline__ __half2 mk2h(__half a, __half b) {
    __half2 r; r.x = a; r.y = b; return r;
}
__device__ __forceinline__ uint32_t packh(float a, float b) {
    __half2 t = __floats2half2_rn(a, b);
    return *reinterpret_cast<uint32_t*>(&t);
}

// ------------------------- conversion kernels -------------------------------
__global__ void split_pair_r12(const float* __restrict__ X,
                               __half* __restrict__ Yh,
                               __half* __restrict__ Yl, size_t n) {
    for (size_t i = (size_t)blockIdx.x * blockDim.x + threadIdx.x; i < n;
         i += (size_t)gridDim.x * blockDim.x) {
        __half hi, lo; split2h(X[i], hi, lo);
        Yh[i] = hi; Yl[i] = lo;
    }
}
__global__ void tohalf_r12(const float* __restrict__ X,
                           __half* __restrict__ Y, size_t n) {
    for (size_t i = (size_t)blockIdx.x * blockDim.x + threadIdx.x; i < n;
         i += (size_t)gridDim.x * blockDim.x)
        Y[i] = __float2half_rn(X[i]);
}

// --------------------------- fp16 2-pass GEMM -------------------------------
// C = (Ah + Al)[M][K] * Bh[K][N] + bias; A segments {hi,lo} over logical K=2048.
// mode: 0 = f32 out; 1 = Q (*0.125, split hi/lo); 2 = V (hi only); 3 = K (hi, transpose)
#define GBM 128
#define GBN 128
#define GBK 32
#define ASTR 40
#define BSTR 136

__global__ __launch_bounds__(256, 2) void gemm2_r12(
    const __half* __restrict__ Ahi, const __half* __restrict__ Alo,
    const __half* __restrict__ Bh,
    const float* __restrict__ bias,
    __half* __restrict__ Chi, __half* __restrict__ Clo,
    float* __restrict__ Cf, int N, int mode)
{
    __shared__ __half As[2][GBM * ASTR];
    __shared__ __half Bs[2][GBK * BSTR];

    const int tid = threadIdx.x, lane = tid & 31, wid = tid >> 5;
    const int wm = wid >> 2, wn = wid & 3;
    const int rowBase = blockIdx.y * GBM, colBase = blockIdx.x * GBN;

    float acc[4][4][4];
#pragma unroll
    for (int a = 0; a < 4; a++)
#pragma unroll
        for (int b = 0; b < 4; b++)
#pragma unroll
            for (int c = 0; c < 4; c++) acc[a][b][c] = 0.f;

    auto loadTiles = [&](int s, int kt) {
        const int seg = kt >> 11, koff = kt & 2047;
        const __half* Ab = seg ? Alo : Ahi;
#pragma unroll
        for (int h = 0; h < 2; h++) {
            int c = tid + h * 256;
            cp16(&As[s][(c >> 2) * ASTR + (c & 3) * 8],
                 &Ab[(size_t)(rowBase + (c >> 2)) * D_MODEL + koff + (c & 3) * 8]);
        }
#pragma unroll
        for (int h = 0; h < 2; h++) {
            int c = tid + h * 256;
            cp16(&Bs[s][(c >> 4) * BSTR + (c & 15) * 8],
                 &Bh[(size_t)(koff + (c >> 4)) * N + colBase + (c & 15) * 8]);
        }
    };

    const int niter = K2 / GBK;      // 128
    loadTiles(0, 0); cp_commit();

    for (int t = 0; t < niter; t++) {
        const int cur = t & 1;
        cp_wait<0>();
        __syncthreads();             // stage cur arrived; all warps done reading 1-cur
        if (t + 1 < niter) { loadTiles(1 - cur, (t + 1) * GBK); cp_commit(); }

        const __half* Ab = As[cur];
        const __half* Bb = Bs[cur];
#pragma unroll
        for (int kk = 0; kk < GBK; kk += 16) {
            uint32_t af[4][4], bf[2][4];
#pragma unroll
            for (int mi = 0; mi < 4; mi++)
                ldmA(af[mi], sptr(&Ab[(wm * 64 + mi * 16 + (lane & 15)) * ASTR
                                      + kk + 8 * (lane >> 4)]));
#pragma unroll
            for (int j = 0; j < 2; j++)
                ldmBT(bf[j], sptr(&Bb[(kk + (lane & 15)) * BSTR
                                      + wn * 32 + j * 16 + 8 * (lane >> 4)]));
#pragma unroll
            for (int mi = 0; mi < 4; mi++)
#pragma unroll
                for (int nj = 0; nj < 4; nj++)
                    mma16816h(acc[mi][nj], af[mi], &bf[nj >> 1][(nj & 1) * 2]);
        }
    }

#pragma unroll
    for (int mi = 0; mi < 4; mi++) {
        int row0 = rowBase + wm * 64 + mi * 16 + (lane >> 2);
#pragma unroll
        for (int nj = 0; nj < 4; nj++) {
            int col = colBase + wn * 32 + nj * 8 + 2 * (lane & 3);
            float bx = bias[col], by = bias[col + 1];
            float v00 = acc[mi][nj][0] + bx, v01 = acc[mi][nj][1] + by;
            float v10 = acc[mi][nj][2] + bx, v11 = acc[mi][nj][3] + by;
            if (mode == 0) {
                *reinterpret_cast<float2*>(Cf + (size_t)row0 * N + col) = make_float2(v00, v01);
                *reinterpret_cast<float2*>(Cf + (size_t)(row0 + 8) * N + col) = make_float2(v10, v11);
            } else if (mode == 1) {
                v00 *= 0.125f; v01 *= 0.125f; v10 *= 0.125f; v11 *= 0.125f;
                __half h00, l00, h01, l01, h10, l10, h11, l11;
                split2h(v00, h00, l00); split2h(v01, h01, l01);
                split2h(v10, h10, l10); split2h(v11, h11, l11);
                *reinterpret_cast<__half2*>(Chi + (size_t)row0 * N + col) = mk2h(h00, h01);
                *reinterpret_cast<__half2*>(Clo + (size_t)row0 * N + col) = mk2h(l00, l01);
                *reinterpret_cast<__half2*>(Chi + (size_t)(row0 + 8) * N + col) = mk2h(h10, h11);
                *reinterpret_cast<__half2*>(Clo + (size_t)(row0 + 8) * N + col) = mk2h(l10, l11);
            } else if (mode == 3) {
                // K: transposed scatter [bg][d][t], hi only
                int b = row0 >> 11, t = row0 & 2047;
                int g = col >> 6,  d = col & 63;
                size_t base0 = ((size_t)(b * 8 + g) * 64 + d) * SEQ;
                size_t base1 = base0 + SEQ;
                Chi[base0 + t]     = __float2half_rn(v00);
                Chi[base1 + t]     = __float2half_rn(v01);
                Chi[base0 + t + 8] = __float2half_rn(v10);
                Chi[base1 + t + 8] = __float2half_rn(v11);
            } else {
                // V: hi only
                *reinterpret_cast<__half2*>(Chi + (size_t)row0 * N + col) =
                    mk2h(__float2half_rn(v00), __float2half_rn(v01));
                *reinterpret_cast<__half2*>(Chi + (size_t)(row0 + 8) * N + col) =
                    mk2h(__float2half_rn(v10), __float2half_rn(v11));
            }
        }
    }
}

// ---------------- flash attention: register softmax, fp16 2-pass ------------
// 256 threads, 8 warps; warp = 16 q-rows x full 64 kv-cols. 2 heads / CTA.
#define FSTR 72

__global__ __launch_bounds__(256) void gqa_flash_r12(
    const __half* __restrict__ Qh, const __half* __restrict__ Ql,
    const __half* __restrict__ KhT, const __half* __restrict__ Vh,
    __half* __restrict__ AOh, __half* __restrict__ AOl)
{
    extern __shared__ char smraw[];
    __half* Qhi = (__half*)smraw;                  // [128][FSTR]
    __half* Qlo = Qhi + 128 * FSTR;
    __half* Khs = Qlo + 128 * FSTR;                // [2][64][FSTR]
    __half* Vhs = Khs + 2 * 64 * FSTR;             // [2][64][FSTR]

    const int tid = threadIdx.x, lane = tid & 31, wid = tid >> 5;
    const int grp = lane >> 2, tq = lane & 3;
    const int qblk = blockIdx.x, hp = blockIdx.y, b = blockIdx.z;
    const int g = hp >> 1;
    const size_t bg = (size_t)(b * 8 + g);
    const int g64 = g * 64;

    auto loadKV = [&](int st, int jb) {
#pragma unroll
        for (int h = 0; h < 2; h++) {
            int c = tid + h * 256;                 // 512 chunks / array
            int r = c >> 3, off8 = (c & 7) * 8;
            size_t ksrc = (bg * 64 + r) * (size_t)SEQ + jb * 64 + off8;
            size_t vsrc = ((size_t)(b * SEQ + jb * 64 + r)) * KV_DIM + g64 + off8;
            cp16(Khs + st * 64 * FSTR + r * FSTR + off8, KhT + ksrc);
            cp16(Vhs + st * 64 * FSTR + r * FSTR + off8, Vh + vsrc);
        }
    };

    loadKV(0, 0); cp_commit();
#pragma unroll
    for (int h = 0; h < 4; h++) {
        int c = tid + h * 256;                     // 1024 chunks
        int r = c >> 3, off8 = (c & 7) * 8;
        size_t src = ((size_t)(b * SEQ + qblk * 64 + (r & 63))) * D_MODEL
                   + (hp * 2 + (r >> 6)) * 64 + off8;
        cp16(Qhi + r * FSTR + off8, Qh + src);
        cp16(Qlo + r * FSTR + off8, Ql + src);
    }
    cp_commit();

    float m0 = -1e30f, m1 = -1e30f, l0 = 0.f, l1 = 0.f;
    float o[8][4];
#pragma unroll
    for (int i = 0; i < 8; i++)
#pragma unroll
        for (int j = 0; j < 4; j++) o[i][j] = 0.f;

    const uint32_t arow = (wid * 16 + (lane & 15)) * FSTR + 8 * (lane >> 4);
    const uint32_t brow = (lane & 15) * FSTR + 8 * (lane >> 4);

    for (int jb = 0; jb < SEQ / 64; jb++) {
        const int cur = jb & 1;
        cp_wait<0>();
        __syncthreads();
        if (jb + 1 < SEQ / 64) { loadKV(1 - cur, jb + 1); cp_commit(); }

        const __half* Kc = Khs + cur * 64 * FSTR;
        const __half* Vc = Vhs + cur * 64 * FSTR;

        // ---- S = (Qh + Ql) @ Kh^T (2-pass) ----
        float s[8][4];
#pragma unroll
        for (int i = 0; i < 8; i++)
#pragma unroll
            for (int j = 0; j < 4; j++) s[i][j] = 0.f;

#pragma unroll
        for (int p = 0; p < 2; p++) {
            const __half* Aseg = p ? Qlo : Qhi;
#pragma unroll
            for (int kk = 0; kk < 4; kk++) {
                uint32_t af[4], bf[4][4];
                ldmA(af, sptr(Aseg + kk * 16 + arow));
#pragma unroll
                for (int j = 0; j < 4; j++)
                    ldmBT(bf[j], sptr(Kc + kk * 16 * FSTR + j * 16 + brow));
#pragma unroll
                for (int nj = 0; nj < 8; nj++)
                    mma16816h(s[nj], af, &bf[nj >> 1][(nj & 1) * 2]);
            }
        }

        // ---- online softmax in registers ----
        float pm0 = -1e30f, pm1 = -1e30f;
#pragma unroll
        for (int nj = 0; nj < 8; nj++) {
            pm0 = fmaxf(pm0, fmaxf(s[nj][0], s[nj][1]));
            pm1 = fmaxf(pm1, fmaxf(s[nj][2], s[nj][3]));
        }
        pm0 = fmaxf(pm0, __shfl_xor_sync(~0u, pm0, 1));
        pm0 = fmaxf(pm0, __shfl_xor_sync(~0u, pm0, 2));
        pm1 = fmaxf(pm1, __shfl_xor_sync(~0u, pm1, 1));
        pm1 = fmaxf(pm1, __shfl_xor_sync(~0u, pm1, 2));
        float mn0 = fmaxf(m0, pm0), mn1 = fmaxf(m1, pm1);
        float corr0 = __expf(m0 - mn0), corr1 = __expf(m1 - mn1);
        m0 = mn0; m1 = mn1;

        float ls0 = 0.f, ls1 = 0.f;
        uint32_t pHi[4][4], pLo[4][4];
#pragma unroll
        for (int nj = 0; nj < 8; nj++) {
            float p0 = __expf(s[nj][0] - mn0);
            float p1 = __expf(s[nj][1] - mn0);
            float p2 = __expf(s[nj][2] - mn1);
            float p3 = __expf(s[nj][3] - mn1);
            ls0 += p0 + p1; ls1 += p2 + p3;
            const int kk = nj >> 1, hf = (nj & 1) * 2;
            uint32_t h01 = packh(p0, p1), h23 = packh(p2, p3);
            pHi[kk][hf]     = h01;
            pHi[kk][hf + 1] = h23;
            __half2 hh01 = *reinterpret_cast<__half2*>(&h01);
            __half2 hh23 = *reinterpret_cast<__half2*>(&h23);
            pLo[kk][hf]     = packh(p0 - __half2float(hh01.x),
                                    p1 - __half2float(hh01.y));
            pLo[kk][hf + 1] = packh(p2 - __half2float(hh23.x),
                                    p3 - __half2float(hh23.y));
        }
        ls0 += __shfl_xor_sync(~0u, ls0, 1); ls0 += __shfl_xor_sync(~0u, ls0, 2);
        ls1 += __shfl_xor_sync(~0u, ls1, 1); ls1 += __shfl_xor_sync(~0u, ls1, 2);
        l0 = l0 * corr0 + ls0;
        l1 = l1 * corr1 + ls1;
#pragma unroll
        for (int nj = 0; nj < 8; nj++) {
            o[nj][0] *= corr0; o[nj][1] *= corr0;
            o[nj][2] *= corr1; o[nj][3] *= corr1;
        }

        // ---- O += (Ph + Pl) @ Vh (2-pass, P in registers) ----
#pragma unroll
        for (int p = 0; p < 2; p++) {
            const uint32_t (*Pa)[4] = p ? pLo : pHi;
#pragma unroll
            for (int kk = 0; kk < 4; kk++) {
                uint32_t bf[4][4];
#pragma unroll
                for (int j = 0; j < 4; j++)
                    ldmBT(bf[j], sptr(Vc + kk * 16 * FSTR + j * 16 + brow));
#pragma unroll
                for (int nj = 0; nj < 8; nj++)
                    mma16816h(o[nj], Pa[kk], &bf[nj >> 1][(nj & 1) * 2]);
            }
        }
    }

    // ---- epilogue: normalize + split-write AO ----
    const int rowa = wid * 16 + grp;
    float il0 = 1.f / l0, il1 = 1.f / l1;
    int head = hp * 2 + (rowa >> 6);
    size_t m0r = (size_t)(b * SEQ + qblk * 64 + (rowa & 63));
#pragma unroll
    for (int nj = 0; nj < 8; nj++) {
        int col = head * 64 + nj * 8 + 2 * tq;
        float v00 = o[nj][0] * il0, v01 = o[nj][1] * il0;
        float v10 = o[nj][2] * il1, v11 = o[nj][3] * il1;
        __half h00, l00, h01, l01, h10, l10, h11, l11;
        split2h(v00, h00, l00); split2h(v01, h01, l01);
        split2h(v10, h10, l10); split2h(v11, h11, l11);
        *reinterpret_cast<__half2*>(AOh + m0r * D_MODEL + col) = mk2h(h00, h01);
        *reinterpret_cast<__half2*>(AOl + m0r * D_MODEL + col) = mk2h(l00, l01);
        *reinterpret_cast<__half2*>(AOh + (m0r + 8) * D_MODEL + col) = mk2h(h10, h11);
        *reinterpret_cast<__half2*>(AOl + (m0r + 8) * D_MODEL + col) = mk2h(l10, l11);
    }
}

// -----------------------------------------------------------------------------
extern "C" void kernel_launch(void* const* d_in, const int* in_sizes, int n_in,
                              void* d_out, int out_size)
{
    (void)in_sizes; (void)n_in; (void)out_size;
    const float* q  = (const float*)d_in[0];
    const float* k  = (const float*)d_in[1];
    const float* v  = (const float*)d_in[2];
    const float* Wq = (const float*)d_in[3];
    const float* bq = (const float*)d_in[4];
    const float* Wk = (const float*)d_in[5];
    const float* bk = (const float*)d_in[6];
    const float* Wv = (const float*)d_in[7];
    const float* bv = (const float*)d_in[8];
    const float* Wo = (const float*)d_in[9];
    const float* bo = (const float*)d_in[10];
    float* out = (float*)d_out;

    __half *qih,*qil,*kih,*kil,*vih,*vil;
    __half *wqh,*wkh,*wvh,*woh;
    __half *Qh,*Ql,*KhT,*Vh,*AOh,*AOl;
    cudaGetSymbolAddress((void**)&qih, s_qih); cudaGetSymbolAddress((void**)&qil, s_qil);
    cudaGetSymbolAddress((void**)&kih, s_kih); cudaGetSymbolAddress((void**)&kil, s_kil);
    cudaGetSymbolAddress((void**)&vih, s_vih); cudaGetSymbolAddress((void**)&vil, s_vil);
    cudaGetSymbolAddress((void**)&wqh, s_wqh); cudaGetSymbolAddress((void**)&wkh, s_wkh);
    cudaGetSymbolAddress((void**)&wvh, s_wvh); cudaGetSymbolAddress((void**)&woh, s_woh);
    cudaGetSymbolAddress((void**)&Qh,  g_Qh);  cudaGetSymbolAddress((void**)&Ql,  g_Ql);
    cudaGetSymbolAddress((void**)&KhT, g_KhT); cudaGetSymbolAddress((void**)&Vh,  g_Vh);
    cudaGetSymbolAddress((void**)&AOh, g_AOh); cudaGetSymbolAddress((void**)&AOl, g_AOl);

    const size_t flash_smem =
        (2 * 128 * FSTR + 2 * 2 * 64 * FSTR) * sizeof(__half);   // 73728
    cudaFuncSetAttribute(gqa_flash_r12, cudaFuncAttributeMaxDynamicSharedMemorySize,
                         (int)flash_smem);

    const size_t nMD = (size_t)M_TOT * D_MODEL;
    const size_t nDD = (size_t)D_MODEL * D_MODEL;
    const size_t nDK = (size_t)D_MODEL * KV_DIM;
    // activations: hi+lo (A side); weights: hi only (B side)
    split_pair_r12<<<2048, 256>>>(q, qih, qil, nMD);
    split_pair_r12<<<2048, 256>>>(k, kih, kil, nMD);
    split_pair_r12<<<2048, 256>>>(v, vih, vil, nMD);
    tohalf_r12<<<2048, 256>>>(Wq, wqh, nDD);
    tohalf_r12<<<512,  256>>>(Wk, wkh, nDK);
    tohalf_r12<<<512,  256>>>(Wv, wvh, nDK);
    tohalf_r12<<<2048, 256>>>(Wo, woh, nDD);

    // projections (fp16 2-pass)
    gemm2_r12<<<dim3(D_MODEL / GBN, M_TOT / GBM), 256>>>(qih, qil, wqh, bq,
        Qh, Ql, nullptr, D_MODEL, 1);
    gemm2_r12<<<dim3(KV_DIM / GBN, M_TOT / GBM), 256>>>(kih, kil, wkh, bk,
        KhT, nullptr, nullptr, KV_DIM, 3);
    gemm2_r12<<<dim3(KV_DIM / GBN, M_TOT / GBM), 256>>>(vih, vil, wvh, bv,
        Vh, nullptr, nullptr, KV_DIM, 2);

    // attention (register softmax, fp16 2-pass, 2 heads per CTA)
    gqa_flash_r12<<<dim3(SEQ / 64, NUM_HEADS / 2, BATCH), 256, flash_smem>>>(
        Qh, Ql, KhT, Vh, AOh, AOl);

    // output projection
    gemm2_r12<<<dim3(D_MODEL / GBN, M_TOT / GBM), 256>>>(AOh, AOl, woh, bo,
        nullptr, nullptr, out, D_MODEL, 0);
}

// round 13
// speedup vs baseline: 3.6613x; 1.1689x over previous
#include <cuda_runtime.h>
#include <cuda_fp16.h>
#include <math.h>
#include <stdint.h>

#define D_MODEL   2048
#define KV_DIM    512
#define HEAD_DIM  64
#define NUM_HEADS 32
#define BATCH     2
#define SEQ       2048
#define M_TOT     (BATCH*SEQ)   // 4096
#define K2        (2*D_MODEL)   // 4096 (2-pass split-K: A={hi,lo} x Bh)

// ---------------- scratch (__device__ globals; no allocation) ---------------
__device__ __half s_qih[(size_t)M_TOT * D_MODEL];
__device__ __half s_qil[(size_t)M_TOT * D_MODEL];
__device__ __half s_kih[(size_t)M_TOT * D_MODEL];
__device__ __half s_kil[(size_t)M_TOT * D_MODEL];
__device__ __half s_vih[(size_t)M_TOT * D_MODEL];
__device__ __half s_vil[(size_t)M_TOT * D_MODEL];
__device__ __half s_wqh[(size_t)D_MODEL * D_MODEL];
__device__ __half s_wkh[(size_t)D_MODEL * KV_DIM];
__device__ __half s_wvh[(size_t)D_MODEL * KV_DIM];
__device__ __half s_woh[(size_t)D_MODEL * D_MODEL];
__device__ __half g_Qh[(size_t)M_TOT * D_MODEL];           // pre-scaled, hi
__device__ __half g_Ql[(size_t)M_TOT * D_MODEL];           // pre-scaled, lo
__device__ __half g_KhT[(size_t)16 * HEAD_DIM * SEQ];      // [bg][d][t], hi only
__device__ __half g_Vh [(size_t)M_TOT * KV_DIM];           // hi only
__device__ __half g_AOh[(size_t)M_TOT * D_MODEL];
__device__ __half g_AOl[(size_t)M_TOT * D_MODEL];

// ------------------------------ helpers -------------------------------------
__device__ __forceinline__ uint32_t sptr(const void* p) {
    return (uint32_t)__cvta_generic_to_shared(p);
}
__device__ __forceinline__ void cp16(void* dst, const void* src) {
    asm volatile("cp.async.cg.shared.global [%0], [%1], 16;"
                 :: "r"(sptr(dst)), "l"(src));
}
__device__ __forceinline__ void cp_commit() { asm volatile("cp.async.commit_group;"); }
template<int N_> __device__ __forceinline__ void cp_wait() {
    asm volatile("cp.async.wait_group %0;" :: "n"(N_));
}
__device__ __forceinline__ void ldmA(uint32_t* r, uint32_t a) {
    asm volatile("ldmatrix.sync.aligned.m8n8.x4.shared.b16 {%0,%1,%2,%3}, [%4];"
                 : "=r"(r[0]), "=r"(r[1]), "=r"(r[2]), "=r"(r[3]) : "r"(a));
}
__device__ __forceinline__ void ldmBT(uint32_t* r, uint32_t a) {
    asm volatile("ldmatrix.sync.aligned.m8n8.x4.trans.shared.b16 {%0,%1,%2,%3}, [%4];"
                 : "=r"(r[0]), "=r"(r[1]), "=r"(r[2]), "=r"(r[3]) : "r"(a));
}
__device__ __forceinline__ void mma16816h(float* c, const uint32_t* a, const uint32_t* b) {
    asm volatile("mma.sync.aligned.m16n8k16.row.col.f32.f16.f16.f32 "
                 "{%0,%1,%2,%3}, {%4,%5,%6,%7}, {%8,%9}, {%0,%1,%2,%3};"
                 : "+f"(c[0]), "+f"(c[1]), "+f"(c[2]), "+f"(c[3])
                 : "r"(a[0]), "r"(a[1]), "r"(a[2]), "r"(a[3]), "r"(b[0]), "r"(b[1]));
}
__device__ __forceinline__ void split2h(float x, __half& hi, __half& lo) {
    hi = __float2half_rn(x);
    lo = __float2half_rn(x - __half2float(hi));
}
__device__ __forceinline__ __half2 mk2h(__half a, __half b) {
    __half2 r; r.x = a; r.y = b; return r;
}
__device__ __forceinline__ uint32_t packh(float a, float b) {
    __half2 t = __floats2half2_rn(a, b);
    return *reinterpret_cast<uint32_t*>(&t);
}

// ------------------------- conversion kernels -------------------------------
// fused q,k,v split (same span)
__global__ void split3_r13(const float* __restrict__ X0, const float* __restrict__ X1,
                           const float* __restrict__ X2,
                           __half* __restrict__ Y0h, __half* __restrict__ Y0l,
                           __half* __restrict__ Y1h, __half* __restrict__ Y1l,
                           __half* __restrict__ Y2h, __half* __restrict__ Y2l,
                           size_t n) {
    for (size_t i = (size_t)blockIdx.x * blockDim.x + threadIdx.x; i < n;
         i += (size_t)gridDim.x * blockDim.x) {
        __half h, l;
        split2h(X0[i], h, l); Y0h[i] = h; Y0l[i] = l;
        split2h(X1[i], h, l); Y1h[i] = h; Y1l[i] = l;
        split2h(X2[i], h, l); Y2h[i] = h; Y2l[i] = l;
    }
}
// fused weight casts: 4 tensors, concatenated logical span
__global__ void tohalf4_r13(const float* __restrict__ W0, __half* __restrict__ Y0, size_t n0,
                            const float* __restrict__ W1, __half* __restrict__ Y1, size_t n1,
                            const float* __restrict__ W2, __half* __restrict__ Y2, size_t n2,
                            const float* __restrict__ W3, __half* __restrict__ Y3, size_t n3) {
    size_t total = n0 + n1 + n2 + n3;
    for (size_t i = (size_t)blockIdx.x * blockDim.x + threadIdx.x; i < total;
         i += (size_t)gridDim.x * blockDim.x) {
        if (i < n0)                Y0[i] = __float2half_rn(W0[i]);
        else if (i < n0 + n1)      Y1[i - n0] = __float2half_rn(W1[i - n0]);
        else if (i < n0 + n1 + n2) Y2[i - n0 - n1] = __float2half_rn(W2[i - n0 - n1]);
        else                       Y3[i - n0 - n1 - n2] = __float2half_rn(W3[i - n0 - n1 - n2]);
    }
}

// --------------------------- fp16 2-pass GEMM -------------------------------
// C = (Ah + Al)[M][K] * Bh[K][N] + bias; A segments {hi,lo} over logical K=2048.
// mode: 0 = f32 out; 1 = Q (*0.125, split hi/lo); 2 = V (hi only); 3 = K (hi, transpose)
#define GBM 128
#define GBN 128
#define GBK 32
#define ASTR 40
#define BSTR 136

__device__ __forceinline__ void gemm2_body(
    const __half* Ahi, const __half* Alo, const __half* Bh,
    const float* bias, __half* Chi, __half* Clo, float* Cf, int N, int mode,
    __half (*As)[GBM * ASTR], __half (*Bs)[GBK * BSTR],
    int rowBase, int colBase)
{
    const int tid = threadIdx.x, lane = tid & 31, wid = tid >> 5;
    const int wm = wid >> 2, wn = wid & 3;

    float acc[4][4][4];
#pragma unroll
    for (int a = 0; a < 4; a++)
#pragma unroll
        for (int b = 0; b < 4; b++)
#pragma unroll
            for (int c = 0; c < 4; c++) acc[a][b][c] = 0.f;

    auto loadTiles = [&](int s, int kt) {
        const int seg = kt >> 11, koff = kt & 2047;
        const __half* Ab = seg ? Alo : Ahi;
#pragma unroll
        for (int h = 0; h < 2; h++) {
            int c = tid + h * 256;
            cp16(&As[s][(c >> 2) * ASTR + (c & 3) * 8],
                 &Ab[(size_t)(rowBase + (c >> 2)) * D_MODEL + koff + (c & 3) * 8]);
        }
#pragma unroll
        for (int h = 0; h < 2; h++) {
            int c = tid + h * 256;
            cp16(&Bs[s][(c >> 4) * BSTR + (c & 15) * 8],
                 &Bh[(size_t)(koff + (c >> 4)) * N + colBase + (c & 15) * 8]);
        }
    };

    const int niter = K2 / GBK;      // 128
    loadTiles(0, 0); cp_commit();

    for (int t = 0; t < niter; t++) {
        const int cur = t & 1;
        cp_wait<0>();
        __syncthreads();
        if (t + 1 < niter) { loadTiles(1 - cur, (t + 1) * GBK); cp_commit(); }

        const __half* Ab = As[cur];
        const __half* Bb = Bs[cur];
#pragma unroll
        for (int kk = 0; kk < GBK; kk += 16) {
            uint32_t af[4][4], bf[2][4];
#pragma unroll
            for (int mi = 0; mi < 4; mi++)
                ldmA(af[mi], sptr(&Ab[(wm * 64 + mi * 16 + (lane & 15)) * ASTR
                                      + kk + 8 * (lane >> 4)]));
#pragma unroll
            for (int j = 0; j < 2; j++)
                ldmBT(bf[j], sptr(&Bb[(kk + (lane & 15)) * BSTR
                                      + wn * 32 + j * 16 + 8 * (lane >> 4)]));
#pragma unroll
            for (int mi = 0; mi < 4; mi++)
#pragma unroll
                for (int nj = 0; nj < 4; nj++)
                    mma16816h(acc[mi][nj], af[mi], &bf[nj >> 1][(nj & 1) * 2]);
        }
    }

#pragma unroll
    for (int mi = 0; mi < 4; mi++) {
        int row0 = rowBase + wm * 64 + mi * 16 + (lane >> 2);
#pragma unroll
        for (int nj = 0; nj < 4; nj++) {
            int col = colBase + wn * 32 + nj * 8 + 2 * (lane & 3);
            float bx = bias[col], by = bias[col + 1];
            float v00 = acc[mi][nj][0] + bx, v01 = acc[mi][nj][1] + by;
            float v10 = acc[mi][nj][2] + bx, v11 = acc[mi][nj][3] + by;
            if (mode == 0) {
                *reinterpret_cast<float2*>(Cf + (size_t)row0 * N + col) = make_float2(v00, v01);
                *reinterpret_cast<float2*>(Cf + (size_t)(row0 + 8) * N + col) = make_float2(v10, v11);
            } else if (mode == 1) {
                v00 *= 0.125f; v01 *= 0.125f; v10 *= 0.125f; v11 *= 0.125f;
                __half h00, l00, h01, l01, h10, l10, h11, l11;
                split2h(v00, h00, l00); split2h(v01, h01, l01);
                split2h(v10, h10, l10); split2h(v11, h11, l11);
                *reinterpret_cast<__half2*>(Chi + (size_t)row0 * N + col) = mk2h(h00, h01);
                *reinterpret_cast<__half2*>(Clo + (size_t)row0 * N + col) = mk2h(l00, l01);
                *reinterpret_cast<__half2*>(Chi + (size_t)(row0 + 8) * N + col) = mk2h(h10, h11);
                *reinterpret_cast<__half2*>(Clo + (size_t)(row0 + 8) * N + col) = mk2h(l10, l11);
            } else if (mode == 3) {
                int b = row0 >> 11, t = row0 & 2047;
                int g = col >> 6,  d = col & 63;
                size_t base0 = ((size_t)(b * 8 + g) * 64 + d) * SEQ;
                size_t base1 = base0 + SEQ;
                Chi[base0 + t]     = __float2half_rn(v00);
                Chi[base1 + t]     = __float2half_rn(v01);
                Chi[base0 + t + 8] = __float2half_rn(v10);
                Chi[base1 + t + 8] = __float2half_rn(v11);
            } else {
                *reinterpret_cast<__half2*>(Chi + (size_t)row0 * N + col) =
                    mk2h(__float2half_rn(v00), __float2half_rn(v01));
                *reinterpret_cast<__half2*>(Chi + (size_t)(row0 + 8) * N + col) =
                    mk2h(__float2half_rn(v10), __float2half_rn(v11));
            }
        }
    }
}

__global__ __launch_bounds__(256, 2) void gemm2_r13(
    const __half* __restrict__ Ahi, const __half* __restrict__ Alo,
    const __half* __restrict__ Bh,
    const float* __restrict__ bias,
    __half* __restrict__ Chi, __half* __restrict__ Clo,
    float* __restrict__ Cf, int N, int mode)
{
    __shared__ __half As[2][GBM * ASTR];
    __shared__ __half Bs[2][GBK * BSTR];
    gemm2_body(Ahi, Alo, Bh, bias, Chi, Clo, Cf, N, mode, As, Bs,
               blockIdx.y * GBM, blockIdx.x * GBN);
}

// merged K+V projection: blockIdx.z = 0 -> K (k-input, mode 3), 1 -> V (v-input, mode 2)
__global__ __launch_bounds__(256, 2) void gemm2_kv_r13(
    const __half* __restrict__ AhiK, const __half* __restrict__ AloK,
    const __half* __restrict__ BhK, const float* __restrict__ biasK,
    __half* __restrict__ CK,
    const __half* __restrict__ AhiV, const __half* __restrict__ AloV,
    const __half* __restrict__ BhV, const float* __restrict__ biasV,
    __half* __restrict__ CV)
{
    __shared__ __half As[2][GBM * ASTR];
    __shared__ __half Bs[2][GBK * BSTR];
    const int z = blockIdx.z;
    gemm2_body(z ? AhiV : AhiK, z ? AloV : AloK, z ? BhV : BhK,
               z ? biasV : biasK, z ? CV : CK, nullptr, nullptr,
               KV_DIM, z ? 2 : 3, As, Bs,
               blockIdx.y * GBM, blockIdx.x * GBN);
}

// ---------------- flash attention: register softmax, fp16 2-pass ------------
// 256 threads, 8 warps; warp = 16 q-rows x full 64 kv-cols. 2 heads / CTA.
// 2 CTAs/SM for latency hiding.
#define FSTR 72

__global__ __launch_bounds__(256, 2) void gqa_flash_r13(
    const __half* __restrict__ Qh, const __half* __restrict__ Ql,
    const __half* __restrict__ KhT, const __half* __restrict__ Vh,
    __half* __restrict__ AOh, __half* __restrict__ AOl)
{
    extern __shared__ char smraw[];
    __half* Qhi = (__half*)smraw;                  // [128][FSTR]
    __half* Qlo = Qhi + 128 * FSTR;
    __half* Khs = Qlo + 128 * FSTR;                // [2][64][FSTR]
    __half* Vhs = Khs + 2 * 64 * FSTR;             // [2][64][FSTR]

    const int tid = threadIdx.x, lane = tid & 31, wid = tid >> 5;
    const int grp = lane >> 2, tq = lane & 3;
    const int qblk = blockIdx.x, hp = blockIdx.y, b = blockIdx.z;
    const int g = hp >> 1;
    const size_t bg = (size_t)(b * 8 + g);
    const int g64 = g * 64;

    auto loadKV = [&](int st, int jb) {
#pragma unroll
        for (int h = 0; h < 2; h++) {
            int c = tid + h * 256;
            int r = c >> 3, off8 = (c & 7) * 8;
            size_t ksrc = (bg * 64 + r) * (size_t)SEQ + jb * 64 + off8;
            size_t vsrc = ((size_t)(b * SEQ + jb * 64 + r)) * KV_DIM + g64 + off8;
            cp16(Khs + st * 64 * FSTR + r * FSTR + off8, KhT + ksrc);
            cp16(Vhs + st * 64 * FSTR + r * FSTR + off8, Vh + vsrc);
        }
    };

    loadKV(0, 0); cp_commit();
#pragma unroll
    for (int h = 0; h < 4; h++) {
        int c = tid + h * 256;
        int r = c >> 3, off8 = (c & 7) * 8;
        size_t src = ((size_t)(b * SEQ + qblk * 64 + (r & 63))) * D_MODEL
                   + (hp * 2 + (r >> 6)) * 64 + off8;
        cp16(Qhi + r * FSTR + off8, Qh + src);
        cp16(Qlo + r * FSTR + off8, Ql + src);
    }
    cp_commit();

    float m0 = -1e30f, m1 = -1e30f, l0 = 0.f, l1 = 0.f;
    float o[8][4];
#pragma unroll
    for (int i = 0; i < 8; i++)
#pragma unroll
        for (int j = 0; j < 4; j++) o[i][j] = 0.f;

    const uint32_t arow = (wid * 16 + (lane & 15)) * FSTR + 8 * (lane >> 4);
    const uint32_t brow = (lane & 15) * FSTR + 8 * (lane >> 4);

    for (int jb = 0; jb < SEQ / 64; jb++) {
        const int cur = jb & 1;
        cp_wait<0>();
        __syncthreads();
        if (jb + 1 < SEQ / 64) { loadKV(1 - cur, jb + 1); cp_commit(); }

        const __half* Kc = Khs + cur * 64 * FSTR;
        const __half* Vc = Vhs + cur * 64 * FSTR;

        // ---- S = (Qh + Ql) @ Kh^T (2-pass) ----
        float s[8][4];
#pragma unroll
        for (int i = 0; i < 8; i++)
#pragma unroll
            for (int j = 0; j < 4; j++) s[i][j] = 0.f;

#pragma unroll
        for (int p = 0; p < 2; p++) {
            const __half* Aseg = p ? Qlo : Qhi;
#pragma unroll
            for (int kk = 0; kk < 4; kk++) {
                uint32_t af[4], bf[4][4];
                ldmA(af, sptr(Aseg + kk * 16 + arow));
#pragma unroll
                for (int j = 0; j < 4; j++)
                    ldmBT(bf[j], sptr(Kc + kk * 16 * FSTR + j * 16 + brow));
#pragma unroll
                for (int nj = 0; nj < 8; nj++)
                    mma16816h(s[nj], af, &bf[nj >> 1][(nj & 1) * 2]);
            }
        }

        // ---- online softmax in registers ----
        float pm0 = -1e30f, pm1 = -1e30f;
#pragma unroll
        for (int nj = 0; nj < 8; nj++) {
            pm0 = fmaxf(pm0, fmaxf(s[nj][0], s[nj][1]));
            pm1 = fmaxf(pm1, fmaxf(s[nj][2], s[nj][3]));
        }
        pm0 = fmaxf(pm0, __shfl_xor_sync(~0u, pm0, 1));
        pm0 = fmaxf(pm0, __shfl_xor_sync(~0u, pm0, 2));
        pm1 = fmaxf(pm1, __shfl_xor_sync(~0u, pm1, 1));
        pm1 = fmaxf(pm1, __shfl_xor_sync(~0u, pm1, 2));
        float mn0 = fmaxf(m0, pm0), mn1 = fmaxf(m1, pm1);
        float corr0 = __expf(m0 - mn0), corr1 = __expf(m1 - mn1);
        m0 = mn0; m1 = mn1;

        float ls0 = 0.f, ls1 = 0.f;
        uint32_t pHi[4][4], pLo[4][4];
#pragma unroll
        for (int nj = 0; nj < 8; nj++) {
            float p0 = __expf(s[nj][0] - mn0);
            float p1 = __expf(s[nj][1] - mn0);
            float p2 = __expf(s[nj][2] - mn1);
            float p3 = __expf(s[nj][3] - mn1);
            ls0 += p0 + p1; ls1 += p2 + p3;
            const int kk = nj >> 1, hf = (nj & 1) * 2;
            uint32_t h01 = packh(p0, p1), h23 = packh(p2, p3);
            pHi[kk][hf]     = h01;
            pHi[kk][hf + 1] = h23;
            __half2 hh01 = *reinterpret_cast<__half2*>(&h01);
            __half2 hh23 = *reinterpret_cast<__half2*>(&h23);
            pLo[kk][hf]     = packh(p0 - __half2float(hh01.x),
                                    p1 - __half2float(hh01.y));
            pLo[kk][hf + 1] = packh(p2 - __half2float(hh23.x),
                                    p3 - __half2float(hh23.y));
        }
        ls0 += __shfl_xor_sync(~0u, ls0, 1); ls0 += __shfl_xor_sync(~0u, ls0, 2);
        ls1 += __shfl_xor_sync(~0u, ls1, 1); ls1 += __shfl_xor_sync(~0u, ls1, 2);
        l0 = l0 * corr0 + ls0;
        l1 = l1 * corr1 + ls1;
#pragma unroll
        for (int nj = 0; nj < 8; nj++) {
            o[nj][0] *= corr0; o[nj][1] *= corr0;
            o[nj][2] *= corr1; o[nj][3] *= corr1;
        }

        // ---- O += (Ph + Pl) @ Vh (2-pass, P in registers) ----
#pragma unroll
        for (int p = 0; p < 2; p++) {
            const uint32_t (*Pa)[4] = p ? pLo : pHi;
#pragma unroll
            for (int kk = 0; kk < 4; kk++) {
                uint32_t bf[4][4];
#pragma unroll
                for (int j = 0; j < 4; j++)
                    ldmBT(bf[j], sptr(Vc + kk * 16 * FSTR + j * 16 + brow));
#pragma unroll
                for (int nj = 0; nj < 8; nj++)
                    mma16816h(o[nj], Pa[kk], &bf[nj >> 1][(nj & 1) * 2]);
            }
        }
    }

    // ---- epilogue: normalize + split-write AO ----
    const int rowa = wid * 16 + grp;
    float il0 = 1.f / l0, il1 = 1.f / l1;
    int head = hp * 2 + (rowa >> 6);
    size_t m0r = (size_t)(b * SEQ + qblk * 64 + (rowa & 63));
#pragma unroll
    for (int nj = 0; nj < 8; nj++) {
        int col = head * 64 + nj * 8 + 2 * tq;
        float v00 = o[nj][0] * il0, v01 = o[nj][1] * il0;
        float v10 = o[nj][2] * il1, v11 = o[nj][3] * il1;
        __half h00, l00, h01, l01, h10, l10, h11, l11;
        split2h(v00, h00, l00); split2h(v01, h01, l01);
        split2h(v10, h10, l10); split2h(v11, h11, l11);
        *reinterpret_cast<__half2*>(AOh + m0r * D_MODEL + col) = mk2h(h00, h01);
        *reinterpret_cast<__half2*>(AOl + m0r * D_MODEL + col) = mk2h(l00, l01);
        *reinterpret_cast<__half2*>(AOh + (m0r + 8) * D_MODEL + col) = mk2h(h10, h11);
        *reinterpret_cast<__half2*>(AOl + (m0r + 8) * D_MODEL + col) = mk2h(l10, l11);
    }
}

// -----------------------------------------------------------------------------
extern "C" void kernel_launch(void* const* d_in, const int* in_sizes, int n_in,
                              void* d_out, int out_size)
{
    (void)in_sizes; (void)n_in; (void)out_size;
    const float* q  = (const float*)d_in[0];
    const float* k  = (const float*)d_in[1];
    const float* v  = (const float*)d_in[2];
    const float* Wq = (const float*)d_in[3];
    const float* bq = (const float*)d_in[4];
    const float* Wk = (const float*)d_in[5];
    const float* bk = (const float*)d_in[6];
    const float* Wv = (const float*)d_in[7];
    const float* bv = (const float*)d_in[8];
    const float* Wo = (const float*)d_in[9];
    const float* bo = (const float*)d_in[10];
    float* out = (float*)d_out;

    __half *qih,*qil,*kih,*kil,*vih,*vil;
    __half *wqh,*wkh,*wvh,*woh;
    __half *Qh,*Ql,*KhT,*Vh,*AOh,*AOl;
    cudaGetSymbolAddress((void**)&qih, s_qih); cudaGetSymbolAddress((void**)&qil, s_qil);
    cudaGetSymbolAddress((void**)&kih, s_kih); cudaGetSymbolAddress((void**)&kil, s_kil);
    cudaGetSymbolAddress((void**)&vih, s_vih); cudaGetSymbolAddress((void**)&vil, s_vil);
    cudaGetSymbolAddress((void**)&wqh, s_wqh); cudaGetSymbolAddress((void**)&wkh, s_wkh);
    cudaGetSymbolAddress((void**)&wvh, s_wvh); cudaGetSymbolAddress((void**)&woh, s_woh);
    cudaGetSymbolAddress((void**)&Qh,  g_Qh);  cudaGetSymbolAddress((void**)&Ql,  g_Ql);
    cudaGetSymbolAddress((void**)&KhT, g_KhT); cudaGetSymbolAddress((void**)&Vh,  g_Vh);
    cudaGetSymbolAddress((void**)&AOh, g_AOh); cudaGetSymbolAddress((void**)&AOl, g_AOl);

    const size_t flash_smem =
        (2 * 128 * FSTR + 2 * 2 * 64 * FSTR) * sizeof(__half);   // 73728
    cudaFuncSetAttribute(gqa_flash_r13, cudaFuncAttributeMaxDynamicSharedMemorySize,
                         (int)flash_smem);

    const size_t nMD = (size_t)M_TOT * D_MODEL;
    const size_t nDD = (size_t)D_MODEL * D_MODEL;
    const size_t nDK = (size_t)D_MODEL * KV_DIM;
    // fused prep: activations hi+lo, weights hi-only
    split3_r13<<<2048, 256>>>(q, k, v, qih, qil, kih, kil, vih, vil, nMD);
    tohalf4_r13<<<2048, 256>>>(Wq, wqh, nDD, Wk, wkh, nDK, Wv, wvh, nDK, Wo, woh, nDD);

    // Q projection
    gemm2_r13<<<dim3(D_MODEL / GBN, M_TOT / GBM), 256>>>(qih, qil, wqh, bq,
        Qh, Ql, nullptr, D_MODEL, 1);
    // K + V projections merged
    gemm2_kv_r13<<<dim3(KV_DIM / GBN, M_TOT / GBM, 2), 256>>>(
        kih, kil, wkh, bk, KhT,
        vih, vil, wvh, bv, Vh);

    // attention (register softmax, fp16 2-pass, 2 heads per CTA, 2 CTA/SM)
    gqa_flash_r13<<<dim3(SEQ / 64, NUM_HEADS / 2, BATCH), 256, flash_smem>>>(
        Qh, Ql, KhT, Vh, AOh, AOl);

    // output projection
    gemm2_r13<<<dim3(D_MODEL / GBN, M_TOT / GBM), 256>>>(AOh, AOl, woh, bo,
        nullptr, nullptr, out, D_MODEL, 0);
}